// round 13
// baseline (speedup 1.0000x reference)
#include <cuda_runtime.h>
#include <cuda_bf16.h>
#include <math.h>
#include <stdint.h>

#define BB      16
#define SS      1024
#define HH      1024
#define HX4     4096
#define NSPAN   32
#define NHEADS  16
#define DHEAD   64
#define NCLS    5
#define NCTA    128
#define UPC     8
#define WSTRIDE 1032   // padded bf16 row stride -> conflict-free ldmatrix (LSTM)
#define GSTRIDE 40     // gates-GEMM SMEM row stride in bf16

// ---------------- device scratch ----------------
__device__ float g_gates[(size_t)BB * SS * HX4];   // [b][s][4H]
__device__ float g_enc  [(size_t)BB * SS * HH];
__device__ __nv_bfloat16 g_xhi[(size_t)BB * SS * HH];
__device__ __nv_bfloat16 g_xlo[(size_t)BB * SS * HH];
__device__ __nv_bfloat16 g_wihhi[(size_t)HX4 * HH];
__device__ __nv_bfloat16 g_wihlo[(size_t)HX4 * HH];
__device__ __nv_bfloat16 g_hhi[2][BB * HH];
__device__ __nv_bfloat16 g_hlo[2][BB * HH];
__device__ int g_flags[NCTA];                      // per-CTA step flags
__device__ float g_pool [BB * NSPAN * HH];
__device__ float g_q    [BB * NSPAN * HH];
__device__ float g_k    [BB * NSPAN * HH];
__device__ float g_v    [BB * NSPAN * HH];
__device__ float g_ctx  [BB * NSPAN * HH];
__device__ float g_wo   [BB * NSPAN * HH];
__device__ float g_attn [BB * NSPAN * HH];

// ---------------- asm helpers ----------------
__device__ __forceinline__ uint32_t f2tf32(float x) {
    uint32_t r; asm("cvt.rna.tf32.f32 %0, %1;" : "=r"(r) : "f"(x)); return r;
}
__device__ __forceinline__ void mma_tf32(float* c, const uint32_t* a, const uint32_t* b) {
    asm volatile("mma.sync.aligned.m16n8k8.row.col.f32.tf32.tf32.f32 "
        "{%0,%1,%2,%3}, {%4,%5,%6,%7}, {%8,%9}, {%0,%1,%2,%3};"
        : "+f"(c[0]), "+f"(c[1]), "+f"(c[2]), "+f"(c[3])
        : "r"(a[0]), "r"(a[1]), "r"(a[2]), "r"(a[3]), "r"(b[0]), "r"(b[1]));
}
__device__ __forceinline__ void mma_bf16(float* c, const uint32_t* a, const uint32_t* b) {
    asm volatile("mma.sync.aligned.m16n8k16.row.col.f32.bf16.bf16.f32 "
        "{%0,%1,%2,%3}, {%4,%5,%6,%7}, {%8,%9}, {%0,%1,%2,%3};"
        : "+f"(c[0]), "+f"(c[1]), "+f"(c[2]), "+f"(c[3])
        : "r"(a[0]), "r"(a[1]), "r"(a[2]), "r"(a[3]), "r"(b[0]), "r"(b[1]));
}
__device__ __forceinline__ void ldsm_x4(uint32_t* r, uint32_t addr) {
    asm volatile("ldmatrix.sync.aligned.m8n8.x4.shared.b16 {%0,%1,%2,%3}, [%4];"
        : "=r"(r[0]), "=r"(r[1]), "=r"(r[2]), "=r"(r[3]) : "r"(addr));
}
__device__ __forceinline__ uint32_t smem_u32(const void* p) {
    uint32_t a;
    asm("{ .reg .u64 t; cvta.to.shared.u64 t, %1; cvt.u32.u64 %0, t; }" : "=r"(a) : "l"(p));
    return a;
}
__device__ __forceinline__ void bsplit(float w, __nv_bfloat16& hi, __nv_bfloat16& lo) {
    hi = __float2bfloat16(w);
    lo = __float2bfloat16(w - __bfloat162float(hi));
}
__device__ __forceinline__ int ld_acq(const int* p) {
    int v; asm volatile("ld.acquire.gpu.global.b32 %0, [%1];" : "=r"(v) : "l"(p)); return v;
}
__device__ __forceinline__ void st_rel(int* p, int v) {
    asm volatile("st.release.gpu.global.b32 [%0], %1;" :: "l"(p), "r"(v) : "memory");
}
__device__ __forceinline__ void cp16(uint32_t s, const void* g) {
    asm volatile("cp.async.cg.shared.global [%0], [%1], 16;" :: "r"(s), "l"(g));
}
#define CP_COMMIT() asm volatile("cp.async.commit_group;" ::: "memory")
#define CP_WAIT(n)  asm volatile("cp.async.wait_group %0;" :: "n"(n) : "memory")
#define BAR_SYNC(id, cnt) asm volatile("bar.sync %0, %1;" :: "r"(id), "r"(cnt) : "memory")

// ============ fp32 -> bf16 hi/lo splitter (+ flag reset in block 0) ============
__global__ void __launch_bounds__(256)
split_kernel(const float* __restrict__ src, __nv_bfloat16* __restrict__ hi,
             __nv_bfloat16* __restrict__ lo, int n4)
{
    if (blockIdx.x == 0 && threadIdx.x < NCTA) g_flags[threadIdx.x] = 0;
    for (int i = blockIdx.x * 256 + threadIdx.x; i < n4; i += gridDim.x * 256) {
        const float4 v = ((const float4*)src)[i];
        __nv_bfloat16 hb[4], lb[4];
        bsplit(v.x, hb[0], lb[0]);
        bsplit(v.y, hb[1], lb[1]);
        bsplit(v.z, hb[2], lb[2]);
        bsplit(v.w, hb[3], lb[3]);
        *(uint2*)(hi + 4 * (size_t)i) = *(uint2*)hb;
        *(uint2*)(lo + 4 * (size_t)i) = *(uint2*)lb;
    }
}

// =====================================================================
// Split-bf16 gates GEMM
// =====================================================================
__global__ void __launch_bounds__(256)
bf16_gemm_gates(const float* __restrict__ b1, const float* __restrict__ b2,
                float* __restrict__ C)
{
    extern __shared__ __nv_bfloat16 sm[];
    const int ASZ = 128 * GSTRIDE;
    const uint32_t BUFB = ASZ * 2;
    const uint32_t base = smem_u32(sm);
    const uint32_t oAhi = 0, oAlo = 2 * BUFB, oWhi = 4 * BUFB, oWlo = 6 * BUFB;

    const int tid = threadIdx.x;
    const int lane = tid & 31, warp = tid >> 5;
    const int wm = (warp >> 2) * 64;
    const int wnn = (warp & 3) * 32;
    const int tig = lane & 3, grp = lane >> 2;

    const int n0 = blockIdx.x * 128, m0 = blockIdx.y * 128;

    const int ldr = tid >> 1;
    const int ldc = (tid & 1) * 16;
    const uint32_t dst_off = (uint32_t)ldr * (GSTRIDE * 2) + ldc * 2;
    const __nv_bfloat16* srcAhi = g_xhi + (size_t)(m0 + ldr) * HH + ldc;
    const __nv_bfloat16* srcAlo = g_xlo + (size_t)(m0 + ldr) * HH + ldc;
    const __nv_bfloat16* srcWhi = g_wihhi + (size_t)(n0 + ldr) * HH + ldc;
    const __nv_bfloat16* srcWlo = g_wihlo + (size_t)(n0 + ldr) * HH + ldc;

    const uint32_t a_roff = (uint32_t)(lane & 15) * (GSTRIDE * 2) + (lane >> 4) * 16;
    const uint32_t aHi0 = base + oAhi + (uint32_t)wm * (GSTRIDE * 2) + a_roff;
    const uint32_t aLo0 = base + oAlo + (uint32_t)wm * (GSTRIDE * 2) + a_roff;
    const uint32_t b_roff = (uint32_t)(lane & 7) * (GSTRIDE * 2) + ((lane >> 3) & 1) * 16;
    const uint32_t bSel0 = base + ((lane < 16) ? oWhi : oWlo)
                         + (uint32_t)wnn * (GSTRIDE * 2) + b_roff;

    float c[4][4][4];
#pragma unroll
    for (int mi = 0; mi < 4; mi++)
#pragma unroll
        for (int ni = 0; ni < 4; ni++)
#pragma unroll
            for (int j = 0; j < 4; j++) c[mi][ni][j] = 0.f;

    {
        const uint32_t d = base + dst_off;
        cp16(d + oAhi, srcAhi);  cp16(d + oAhi + 16, srcAhi + 8);
        cp16(d + oAlo, srcAlo);  cp16(d + oAlo + 16, srcAlo + 8);
        cp16(d + oWhi, srcWhi);  cp16(d + oWhi + 16, srcWhi + 8);
        cp16(d + oWlo, srcWlo);  cp16(d + oWlo + 16, srcWlo + 8);
        CP_COMMIT();
    }

    for (int s = 0; s < 32; s++) {
        CP_WAIT(0);
        __syncthreads();

        if (s + 1 < 32) {
            const int k = (s + 1) * 32;
            const uint32_t d = base + ((s + 1) & 1) * BUFB + dst_off;
            cp16(d + oAhi, srcAhi + k);  cp16(d + oAhi + 16, srcAhi + k + 8);
            cp16(d + oAlo, srcAlo + k);  cp16(d + oAlo + 16, srcAlo + k + 8);
            cp16(d + oWhi, srcWhi + k);  cp16(d + oWhi + 16, srcWhi + k + 8);
            cp16(d + oWlo, srcWlo + k);  cp16(d + oWlo + 16, srcWlo + k + 8);
            CP_COMMIT();
        }

        const uint32_t bo = (uint32_t)(s & 1) * BUFB;
#pragma unroll
        for (int kk = 0; kk < 2; kk++) {
            const uint32_t ko = kk * 32;
            uint32_t ah[4][4], al[4][4], bb[4][4];
#pragma unroll
            for (int mi = 0; mi < 4; mi++) {
                ldsm_x4(ah[mi], aHi0 + bo + ko + mi * 16 * (GSTRIDE * 2));
                ldsm_x4(al[mi], aLo0 + bo + ko + mi * 16 * (GSTRIDE * 2));
            }
#pragma unroll
            for (int ni = 0; ni < 4; ni++)
                ldsm_x4(bb[ni], bSel0 + bo + ko + ni * 8 * (GSTRIDE * 2));
#pragma unroll
            for (int mi = 0; mi < 4; mi++)
#pragma unroll
                for (int ni = 0; ni < 4; ni++) {
                    mma_bf16(c[mi][ni], ah[mi], bb[ni]);
                    mma_bf16(c[mi][ni], al[mi], bb[ni]);
                    mma_bf16(c[mi][ni], ah[mi], bb[ni] + 2);
                }
        }
        __syncthreads();
    }

#pragma unroll
    for (int ni = 0; ni < 4; ni++) {
        const int col = n0 + wnn + ni * 8 + tig * 2;
        const float bias0 = b1[col] + b2[col];
        const float bias1 = b1[col + 1] + b2[col + 1];
#pragma unroll
        for (int mi = 0; mi < 4; mi++) {
            const int row = m0 + wm + mi * 16 + grp;
            C[(size_t)row * HX4 + col]           = c[mi][ni][0] + bias0;
            C[(size_t)row * HX4 + col + 1]       = c[mi][ni][1] + bias1;
            C[(size_t)(row + 8) * HX4 + col]     = c[mi][ni][2] + bias0;
            C[(size_t)(row + 8) * HX4 + col + 1] = c[mi][ni][3] + bias1;
        }
    }
}

// =====================================================================
// tf32 GEMM (QKV / Wo)
// =====================================================================
__device__ __forceinline__ void gemm_body(
    const float* __restrict__ A, const float* __restrict__ W,
    const float* __restrict__ b1, const float* __restrict__ b2,
    float* __restrict__ C, int N, int K,
    uint32_t (*As)[136], uint32_t (*Ws)[136])
{
    const int tid = threadIdx.x;
    const int lane = tid & 31, warp = tid >> 5;
    const int wm = (warp >> 2) * 64;
    const int wnn = (warp & 3) * 32;
    const int tig = lane & 3, grp = lane >> 2;

    const int n0 = blockIdx.x * 128, m0 = blockIdx.y * 128;
    const int lr = tid >> 1;
    const int kq = (tid & 1) * 8;

    float c[4][4][4];
#pragma unroll
    for (int mi = 0; mi < 4; mi++)
#pragma unroll
        for (int ni = 0; ni < 4; ni++)
#pragma unroll
            for (int j = 0; j < 4; j++) c[mi][ni][j] = 0.f;

    const float* Ap = A + (size_t)(m0 + lr) * K + kq;
    const float* Wp = W + (size_t)(n0 + lr) * K + kq;

    float4 av0 = *(const float4*)(Ap);
    float4 av1 = *(const float4*)(Ap + 4);
    float4 wv0 = *(const float4*)(Wp);
    float4 wv1 = *(const float4*)(Wp + 4);

    for (int k0 = 0; k0 < K; k0 += 16) {
        As[kq+0][lr] = f2tf32(av0.x); As[kq+1][lr] = f2tf32(av0.y);
        As[kq+2][lr] = f2tf32(av0.z); As[kq+3][lr] = f2tf32(av0.w);
        As[kq+4][lr] = f2tf32(av1.x); As[kq+5][lr] = f2tf32(av1.y);
        As[kq+6][lr] = f2tf32(av1.z); As[kq+7][lr] = f2tf32(av1.w);
        Ws[kq+0][lr] = f2tf32(wv0.x); Ws[kq+1][lr] = f2tf32(wv0.y);
        Ws[kq+2][lr] = f2tf32(wv0.z); Ws[kq+3][lr] = f2tf32(wv0.w);
        Ws[kq+4][lr] = f2tf32(wv1.x); Ws[kq+5][lr] = f2tf32(wv1.y);
        Ws[kq+6][lr] = f2tf32(wv1.z); Ws[kq+7][lr] = f2tf32(wv1.w);
        __syncthreads();

        if (k0 + 16 < K) {
            av0 = *(const float4*)(Ap + k0 + 16);
            av1 = *(const float4*)(Ap + k0 + 20);
            wv0 = *(const float4*)(Wp + k0 + 16);
            wv1 = *(const float4*)(Wp + k0 + 20);
        }

#pragma unroll
        for (int ks = 0; ks < 16; ks += 8) {
            uint32_t a[4][4], b[4][2];
#pragma unroll
            for (int mi = 0; mi < 4; mi++) {
                const int rb = wm + mi * 16 + grp;
                a[mi][0] = As[ks + tig][rb];
                a[mi][1] = As[ks + tig][rb + 8];
                a[mi][2] = As[ks + tig + 4][rb];
                a[mi][3] = As[ks + tig + 4][rb + 8];
            }
#pragma unroll
            for (int ni = 0; ni < 4; ni++) {
                const int nb = wnn + ni * 8 + grp;
                b[ni][0] = Ws[ks + tig][nb];
                b[ni][1] = Ws[ks + tig + 4][nb];
            }
#pragma unroll
            for (int mi = 0; mi < 4; mi++)
#pragma unroll
                for (int ni = 0; ni < 4; ni++)
                    mma_tf32(c[mi][ni], a[mi], b[ni]);
        }
        __syncthreads();
    }

#pragma unroll
    for (int ni = 0; ni < 4; ni++) {
        const int col = n0 + wnn + ni * 8 + tig * 2;
        float bias0 = b1[col], bias1 = b1[col + 1];
        if (b2) { bias0 += b2[col]; bias1 += b2[col + 1]; }
#pragma unroll
        for (int mi = 0; mi < 4; mi++) {
            const int row = m0 + wm + mi * 16 + grp;
            C[(size_t)row * N + col]           = c[mi][ni][0] + bias0;
            C[(size_t)row * N + col + 1]       = c[mi][ni][1] + bias1;
            C[(size_t)(row + 8) * N + col]     = c[mi][ni][2] + bias0;
            C[(size_t)(row + 8) * N + col + 1] = c[mi][ni][3] + bias1;
        }
    }
}

__global__ void __launch_bounds__(256)
mma_gemm_nt(const float* __restrict__ A, const float* __restrict__ W,
            const float* __restrict__ b1, const float* __restrict__ b2,
            float* __restrict__ C, int N, int K)
{
    __shared__ uint32_t As[16][136];
    __shared__ uint32_t Ws[16][136];
    gemm_body(A, W, b1, b2, C, N, K, As, Ws);
}

__global__ void __launch_bounds__(256)
mma_gemm_qkv(const float* __restrict__ A,
             const float* __restrict__ Wq, const float* __restrict__ Wk, const float* __restrict__ Wv,
             const float* __restrict__ bq, const float* __restrict__ bk, const float* __restrict__ bv,
             float* __restrict__ Oq, float* __restrict__ Ok, float* __restrict__ Ov)
{
    __shared__ uint32_t As[16][136];
    __shared__ uint32_t Ws[16][136];
    const int z = blockIdx.z;
    const float* W = (z == 0) ? Wq : (z == 1) ? Wk : Wv;
    const float* b = (z == 0) ? bq : (z == 1) ? bk : bv;
    float* O       = (z == 0) ? Oq : (z == 1) ? Ok : Ov;
    gemm_body(A, W, b, nullptr, O, HH, HH, As, Ws);
}

// =====================================================================
// Persistent LSTM: per-CTA flag barrier (st.release publish — no L2
// atomic serialization), group-pipelined staging as R12.
// =====================================================================
__global__ void __launch_bounds__(256, 1)
lstm_kernel(const float* __restrict__ Whh)
{
    extern __shared__ char smraw[];
    __nv_bfloat16* Whi = (__nv_bfloat16*)smraw;
    __nv_bfloat16* Wlo = Whi + 32 * WSTRIDE;
    __nv_bfloat16* hhi = Wlo + 32 * WSTRIDE;
    __nv_bfloat16* hlo = hhi + 16 * WSTRIDE;
    float* gbuf = (float*)(hlo + 16 * WSTRIDE);     // [2][32][17]
    float* cst  = gbuf + 2 * 32 * 17;               // [128]

    const int tid = threadIdx.x;
    const int cta = blockIdx.x;
    const int lane = tid & 31, warp = tid >> 5;
    const int grp = lane >> 2, tig = lane & 3;
    const int gate = warp >> 1;
    const int khalf = warp & 1;

    for (int i = tid; i < 32 * 1024; i += 256) {
        const int r = i >> 10, k = i & 1023;
        const int jrow = (r >> 3) * 1024 + cta * UPC + (r & 7);
        __nv_bfloat16 hi, lo;
        bsplit(Whh[(size_t)jrow * HH + k], hi, lo);
        Whi[r * WSTRIDE + k] = hi;
        Wlo[r * WSTRIDE + k] = lo;
    }
    if (tid < 128) cst[tid] = 0.f;
    __syncthreads();

    const uint32_t s_hhi = smem_u32(hhi), s_hlo = smem_u32(hlo);
    const uint32_t khB = (uint32_t)khalf * 1024;
    const uint32_t a_row = lane & 15;
    const uint32_t a_colB = (lane >> 4) * 16;
    const uint32_t ahi0 = s_hhi + a_row * (WSTRIDE * 2) + a_colB + khB;
    const uint32_t alo0 = s_hlo + a_row * (WSTRIDE * 2) + a_colB + khB;
    const uint32_t brow = (uint32_t)gate * 8 + (lane & 7);
    const uint32_t bsel = (lane < 16) ? smem_u32(Whi) : smem_u32(Wlo);
    const uint32_t b0 = bsel + brow * (WSTRIDE * 2) + ((lane >> 3) & 1) * 16 + khB;

    const int r0 = gate * 8 + tig * 2;
    const int jrow0 = gate * 1024 + cta * UPC + tig * 2;
    const int su = tid & 7, sb = tid >> 3;
    const int unit = cta * UPC + su;
    float* gplane = gbuf + khalf * (32 * 17);

    const int G0 = khalf * 2, G1 = khalf * 2 + 1;   // unit groups this warp consumes
    const int barid = 1 + khalf;

    for (int t = 0; t < SS; t++) {
        float2 gt0 = make_float2(0.f, 0.f), gt1 = make_float2(0.f, 0.f);
        if (khalf == 0) {
            gt0 = *(const float2*)(g_gates + ((size_t)grp       * SS + t) * HX4 + jrow0);
            gt1 = *(const float2*)(g_gates + ((size_t)(grp + 8) * SS + t) * HX4 + jrow0);
        }

        float c[4] = {0.f, 0.f, 0.f, 0.f};
        if (t > 0) {
            const __nv_bfloat16* shi = g_hhi[t & 1];
            const __nv_bfloat16* slo = g_hlo[t & 1];
            const int tgt = t;

            // ---- group G0: poll 32 per-CTA flags (1 line), then stage ----
            for (;;) {
                const bool ok = ld_acq(&g_flags[G0 * 32 + lane]) >= tgt;
                if (__all_sync(0xffffffffu, ok)) break;
            }
#pragma unroll
            for (int j = 0; j < 4; j++) {
                const int row = gate * 4 + j;
                const int col = G0 * 256 + lane * 8;
                cp16(s_hhi + row * (WSTRIDE * 2) + col * 2, shi + row * 1024 + col);
                cp16(s_hlo + row * (WSTRIDE * 2) + col * 2, slo + row * 1024 + col);
            }
            CP_COMMIT();

            // ---- group G1: poll, stage ----
            for (;;) {
                const bool ok = ld_acq(&g_flags[G1 * 32 + lane]) >= tgt;
                if (__all_sync(0xffffffffu, ok)) break;
            }
#pragma unroll
            for (int j = 0; j < 4; j++) {
                const int row = gate * 4 + j;
                const int col = G1 * 256 + lane * 8;
                cp16(s_hhi + row * (WSTRIDE * 2) + col * 2, shi + row * 1024 + col);
                cp16(s_hlo + row * (WSTRIDE * 2) + col * 2, slo + row * 1024 + col);
            }
            CP_COMMIT();

            // ---- MMA first half (G0 cols) ----
            CP_WAIT(1);
            BAR_SYNC(barid, 128);
#pragma unroll 4
            for (int kt = 0; kt < 16; kt++) {
                const uint32_t off = kt * 32;
                uint32_t ah[4], al[4], bb[4];
                ldsm_x4(ah, ahi0 + off);
                ldsm_x4(al, alo0 + off);
                ldsm_x4(bb, b0 + off);
                mma_bf16(c, ah, bb);
                mma_bf16(c, al, bb);
                mma_bf16(c, ah, bb + 2);
            }
            // ---- MMA second half (G1 cols) ----
            CP_WAIT(0);
            BAR_SYNC(barid, 128);
#pragma unroll 4
            for (int kt = 16; kt < 32; kt++) {
                const uint32_t off = kt * 32;
                uint32_t ah[4], al[4], bb[4];
                ldsm_x4(ah, ahi0 + off);
                ldsm_x4(al, alo0 + off);
                ldsm_x4(bb, b0 + off);
                mma_bf16(c, ah, bb);
                mma_bf16(c, al, bb);
                mma_bf16(c, ah, bb + 2);
            }
        }

        gplane[(r0    ) * 17 + grp    ] = c[0] + gt0.x;
        gplane[(r0 + 1) * 17 + grp    ] = c[1] + gt0.y;
        gplane[(r0    ) * 17 + grp + 8] = c[2] + gt1.x;
        gplane[(r0 + 1) * 17 + grp + 8] = c[3] + gt1.y;
        __syncthreads();

        float h = 0.f;
        if (tid < 128) {
            const float iv = gbuf[(0 * 8 + su) * 17 + sb] + gbuf[32*17 + (0 * 8 + su) * 17 + sb];
            const float fv = gbuf[(1 * 8 + su) * 17 + sb] + gbuf[32*17 + (1 * 8 + su) * 17 + sb];
            const float gv = gbuf[(2 * 8 + su) * 17 + sb] + gbuf[32*17 + (2 * 8 + su) * 17 + sb];
            const float ov = gbuf[(3 * 8 + su) * 17 + sb] + gbuf[32*17 + (3 * 8 + su) * 17 + sb];
            const float ig = 1.f / (1.f + expf(-iv));
            const float fg = 1.f / (1.f + expf(-fv));
            const float og = 1.f / (1.f + expf(-ov));
            const float cv = fg * cst[tid] + ig * tanhf(gv);
            cst[tid] = cv;
            h = og * tanhf(cv);
            __nv_bfloat16 hi, lo;
            bsplit(h, hi, lo);
            g_hhi[(t + 1) & 1][sb * HH + unit] = hi;
            g_hlo[(t + 1) & 1][sb * HH + unit] = lo;
        }
        __syncthreads();
        if (tid == 0) st_rel(&g_flags[cta], t + 1);   // per-CTA flag: no atomic drain
        if (tid < 128)
            g_enc[((size_t)sb * SS + t) * HH + unit] = h;
    }
}

// ============ block reduction helper (256 threads) ============
__device__ __forceinline__ float blk_sum256(float v, float* red)
{
#pragma unroll
    for (int o = 16; o > 0; o >>= 1) v += __shfl_down_sync(0xffffffffu, v, o);
    const int tid = threadIdx.x;
    if ((tid & 31) == 0) red[tid >> 5] = v;
    __syncthreads();
    if (tid < 32) {
        float x = (tid < 8) ? red[tid] : 0.f;
#pragma unroll
        for (int o = 4; o > 0; o >>= 1) x += __shfl_down_sync(0xffffffffu, x, o);
        if (tid == 0) red[0] = x;
    }
    __syncthreads();
    const float s = red[0];
    __syncthreads();
    return s;
}

// ============ span mean-pool + LayerNorm ============
__global__ void pool_ln_kernel(const float* __restrict__ gamma, const float* __restrict__ beta,
                               const int* __restrict__ heads, const int* __restrict__ tails)
{
    __shared__ float red[32];
    const int span = blockIdx.x;
    const int tid = threadIdx.x;
    const int b = span >> 5;
    const int head = heads[span], tail = tails[span];

    float4 acc = make_float4(0.f, 0.f, 0.f, 0.f);
    for (int s = head + 1; s < tail; s++) {
        const float4 v = *(const float4*)(g_enc + ((size_t)b * SS + s) * HH + tid * 4);
        acc.x += v.x; acc.y += v.y; acc.z += v.z; acc.w += v.w;
    }
    const float invc = 1.f / (float)(tail - head - 1);
    acc.x *= invc; acc.y *= invc; acc.z *= invc; acc.w *= invc;

    const float mu = blk_sum256(acc.x + acc.y + acc.z + acc.w, red) * (1.f / HH);
    const float dx = acc.x - mu, dy = acc.y - mu, dz = acc.z - mu, dw = acc.w - mu;
    const float var = blk_sum256(dx*dx + dy*dy + dz*dz + dw*dw, red) * (1.f / HH);
    const float rstd = rsqrtf(var + 1e-7f);

    const int h = tid * 4;
    const float4 gm = *(const float4*)(gamma + h);
    const float4 bt = *(const float4*)(beta + h);
    float4 o = make_float4(dx*rstd*gm.x + bt.x, dy*rstd*gm.y + bt.y,
                           dz*rstd*gm.z + bt.z, dw*rstd*gm.w + bt.w);
    *(float4*)(g_pool + (size_t)span * HH + h) = o;
}

// ============ residual LayerNorm ============
__global__ void ln_res_kernel(const float* __restrict__ gamma, const float* __restrict__ beta)
{
    __shared__ float red[32];
    const int row = blockIdx.x;
    const int tid = threadIdx.x;
    const size_t off = (size_t)row * HH + tid * 4;

    float4 x = *(const float4*)(g_wo + off);
    const float4 p = *(const float4*)(g_pool + off);
    x.x += p.x; x.y += p.y; x.z += p.z; x.w += p.w;

    const float mu = blk_sum256(x.x + x.y + x.z + x.w, red) * (1.f / HH);
    const float dx = x.x - mu, dy = x.y - mu, dz = x.z - mu, dw = x.w - mu;
    const float var = blk_sum256(dx*dx + dy*dy + dz*dz + dw*dw, red) * (1.f / HH);
    const float rstd = rsqrtf(var + 1e-7f);

    const int h = tid * 4;
    const float4 gm = *(const float4*)(gamma + h);
    const float4 bt = *(const float4*)(beta + h);
    float4 o = make_float4(dx*rstd*gm.x + bt.x, dy*rstd*gm.y + bt.y,
                           dz*rstd*gm.z + bt.z, dw*rstd*gm.w + bt.w);
    *(float4*)(g_attn + off) = o;
}

// ============ span attention: one CTA per (b, head) ============
__global__ void attn_kernel(const int* __restrict__ mask)
{
    __shared__ float Qs[32][65], Ks[32][65], Vs[32][65];
    __shared__ float P[32][33];
    __shared__ int ms[32];

    const int bh = blockIdx.x;
    const int b = bh / NHEADS, hd = bh % NHEADS;
    const int tid = threadIdx.x;
    const size_t rowbase = (size_t)b * NSPAN;
    const int col0 = hd * DHEAD;

    for (int i = tid; i < NSPAN * DHEAD; i += 128) {
        const int n = i >> 6, d = i & 63;
        const size_t off = (rowbase + n) * HH + col0 + d;
        Qs[n][d] = g_q[off];
        Ks[n][d] = g_k[off];
        Vs[n][d] = g_v[off];
    }
    if (tid < 32) ms[tid] = mask[b * NSPAN + tid];
    __syncthreads();

    for (int i = tid; i < 1024; i += 128) {
        const int qi = i >> 5, kj = i & 31;
        float s = 0.f;
#pragma unroll
        for (int d = 0; d < 64; d++) s += Qs[qi][d] * Ks[kj][d];
        s *= 0.125f;
        P[qi][kj] = (ms[qi] && ms[kj]) ? s : -3.402823466e38f;
    }
    __syncthreads();

    if (tid < 32) {
        float mx = -3.402823466e38f;
#pragma unroll
        for (int j = 0; j < 32; j++) mx = fmaxf(mx, P[tid][j]);
        float sum = 0.f;
#pragma unroll
        for (int j = 0; j < 32; j++) { float e = expf(P[tid][j] - mx); P[tid][j] = e; sum += e; }
        const float inv = 1.f / sum;
#pragma unroll
        for (int j = 0; j < 32; j++) P[tid][j] = (ms[tid] && ms[j]) ? P[tid][j] * inv : 0.f;
    }
    __syncthreads();

    for (int i = tid; i < NSPAN * DHEAD; i += 128) {
        const int qi = i >> 6, d = i & 63;
        float s = 0.f;
#pragma unroll
        for (int j = 0; j < 32; j++) s += P[qi][j] * Vs[j][d];
        g_ctx[(rowbase + qi) * HH + col0 + d] = s;
    }
}

// ============ classifier: warp per row, N=5 ============
__global__ void __launch_bounds__(256)
clf_kernel(const float* __restrict__ W, const float* __restrict__ b, float* __restrict__ out)
{
    __shared__ float ws[NCLS * HH];
    const int tid = threadIdx.x;
    for (int i = tid; i < NCLS * HH; i += 256) ws[i] = W[i];
    __syncthreads();

    const int warp = tid >> 5, lane = tid & 31;
    const int row = blockIdx.x * 8 + warp;
    const float* a = g_attn + (size_t)row * HH;

    float acc[NCLS] = {0.f, 0.f, 0.f, 0.f, 0.f};
    for (int k = lane; k < HH; k += 32) {
        const float av = a[k];
#pragma unroll
        for (int c = 0; c < NCLS; c++) acc[c] += av * ws[c * HH + k];
    }
#pragma unroll
    for (int c = 0; c < NCLS; c++) {
#pragma unroll
        for (int o = 16; o > 0; o >>= 1) acc[c] += __shfl_down_sync(0xffffffffu, acc[c], o);
    }
    if (lane == 0) {
#pragma unroll
        for (int c = 0; c < NCLS; c++) out[(size_t)row * NCLS + c] = acc[c] + b[c];
    }
}

// ============ launch ============
extern "C" void kernel_launch(void* const* d_in, const int* in_sizes, int n_in,
                              void* d_out, int out_size)
{
    const float* enc_in  = (const float*)d_in[0];
    const float* W_ih    = (const float*)d_in[1];
    const float* W_hh    = (const float*)d_in[2];
    const float* b_ih    = (const float*)d_in[3];
    const float* b_hh    = (const float*)d_in[4];
    const float* ln_g    = (const float*)d_in[5];
    const float* ln_b    = (const float*)d_in[6];
    const float* Wq      = (const float*)d_in[7];
    const float* bq      = (const float*)d_in[8];
    const float* Wk      = (const float*)d_in[9];
    const float* bk      = (const float*)d_in[10];
    const float* Wv      = (const float*)d_in[11];
    const float* bv      = (const float*)d_in[12];
    const float* Wo      = (const float*)d_in[13];
    const float* bo      = (const float*)d_in[14];
    const float* aln_g   = (const float*)d_in[15];
    const float* aln_b   = (const float*)d_in[16];
    const float* clf_W   = (const float*)d_in[17];
    const float* clf_b   = (const float*)d_in[18];
    const int*   heads   = (const int*)d_in[19];
    const int*   tails   = (const int*)d_in[20];
    const int*   mask    = (const int*)d_in[21];
    float* out = (float*)d_out;

    float *gates, *pool, *q, *k, *v, *ctx, *wo_buf;
    __nv_bfloat16 *xhi, *xlo, *whi, *wlo;
    cudaGetSymbolAddress((void**)&gates,  g_gates);
    cudaGetSymbolAddress((void**)&pool,   g_pool);
    cudaGetSymbolAddress((void**)&q,      g_q);
    cudaGetSymbolAddress((void**)&k,      g_k);
    cudaGetSymbolAddress((void**)&v,      g_v);
    cudaGetSymbolAddress((void**)&ctx,    g_ctx);
    cudaGetSymbolAddress((void**)&wo_buf, g_wo);
    cudaGetSymbolAddress((void**)&xhi,    g_xhi);
    cudaGetSymbolAddress((void**)&xlo,    g_xlo);
    cudaGetSymbolAddress((void**)&whi,    g_wihhi);
    cudaGetSymbolAddress((void**)&wlo,    g_wihlo);

    // 0-1. split X and W_ih into bf16 hi/lo (flag reset folded into block 0)
    split_kernel<<<2048, 256>>>(enc_in, xhi, xlo, (BB * SS * HH) / 4);
    split_kernel<<<1024, 256>>>(W_ih, whi, wlo, (HX4 * HH) / 4);

    // 2. gates = X @ W_ih^T + b_ih + b_hh (split-bf16)
    const int gsmem = 8 * 128 * GSTRIDE * (int)sizeof(__nv_bfloat16);
    cudaFuncSetAttribute(bf16_gemm_gates, cudaFuncAttributeMaxDynamicSharedMemorySize, gsmem);
    bf16_gemm_gates<<<dim3(HX4 / 128, (BB * SS) / 128), 256, gsmem>>>(b_ih, b_hh, gates);

    // 3. persistent LSTM
    const int smem = (32 * WSTRIDE * 2 + 16 * WSTRIDE * 2) * (int)sizeof(__nv_bfloat16)
                   + (2 * 32 * 17 + 128) * (int)sizeof(float);
    cudaFuncSetAttribute(lstm_kernel, cudaFuncAttributeMaxDynamicSharedMemorySize, smem);
    lstm_kernel<<<NCTA, 256, smem>>>(W_hh);

    // 4. span pool + LN
    pool_ln_kernel<<<BB * NSPAN, 256>>>(ln_g, ln_b, heads, tails);

    // 5. fused QKV projections (tf32)
    mma_gemm_qkv<<<dim3(HH / 128, (BB * NSPAN) / 128, 3), 256>>>(
        pool, Wq, Wk, Wv, bq, bk, bv, q, k, v);

    // 6. attention
    attn_kernel<<<BB * NHEADS, 128>>>(mask);

    // 7. output projection (tf32)
    mma_gemm_nt<<<dim3(HH / 128, (BB * NSPAN) / 128), 256>>>(ctx, Wo, bo, nullptr, wo_buf, HH, HH);

    // 8. residual LN
    ln_res_kernel<<<BB * NSPAN, 256>>>(aln_g, aln_b);

    // 9. classifier -> d_out [B,NS,L]
    clf_kernel<<<(BB * NSPAN) / 8, 256>>>(clf_W, clf_b, out);
}

// round 14
// speedup vs baseline: 1.7102x; 1.7102x over previous
#include <cuda_runtime.h>
#include <cuda_bf16.h>
#include <math.h>
#include <stdint.h>

#define BB      16
#define SS      1024
#define HH      1024
#define HX4     4096
#define NSPAN   32
#define NHEADS  16
#define DHEAD   64
#define NCLS    5
#define NCTA    128
#define UPC     8
#define WSTRIDE 1032   // padded bf16 row stride -> conflict-free ldmatrix

// ---------------- device scratch ----------------
__device__ float g_gates[(size_t)BB * SS * HX4];   // [b][s][4H]
__device__ float g_enc  [(size_t)BB * SS * HH];
__device__ __nv_bfloat16 g_hhi[2][BB * HH];
__device__ __nv_bfloat16 g_hlo[2][BB * HH];
__device__ int g_cnt[4 * 32];                      // 4 group counters, 128B apart
__device__ float g_pool [BB * NSPAN * HH];
__device__ float g_q    [BB * NSPAN * HH];
__device__ float g_k    [BB * NSPAN * HH];
__device__ float g_v    [BB * NSPAN * HH];
__device__ float g_ctx  [BB * NSPAN * HH];
__device__ float g_wo   [BB * NSPAN * HH];
__device__ float g_attn [BB * NSPAN * HH];

// ---------------- asm helpers ----------------
__device__ __forceinline__ uint32_t f2tf32(float x) {
    uint32_t r; asm("cvt.rna.tf32.f32 %0, %1;" : "=r"(r) : "f"(x)); return r;
}
__device__ __forceinline__ void mma_tf32(float* c, const uint32_t* a, const uint32_t* b) {
    asm volatile("mma.sync.aligned.m16n8k8.row.col.f32.tf32.tf32.f32 "
        "{%0,%1,%2,%3}, {%4,%5,%6,%7}, {%8,%9}, {%0,%1,%2,%3};"
        : "+f"(c[0]), "+f"(c[1]), "+f"(c[2]), "+f"(c[3])
        : "r"(a[0]), "r"(a[1]), "r"(a[2]), "r"(a[3]), "r"(b[0]), "r"(b[1]));
}
__device__ __forceinline__ void mma_bf16(float* c, const uint32_t* a, const uint32_t* b) {
    asm volatile("mma.sync.aligned.m16n8k16.row.col.f32.bf16.bf16.f32 "
        "{%0,%1,%2,%3}, {%4,%5,%6,%7}, {%8,%9}, {%0,%1,%2,%3};"
        : "+f"(c[0]), "+f"(c[1]), "+f"(c[2]), "+f"(c[3])
        : "r"(a[0]), "r"(a[1]), "r"(a[2]), "r"(a[3]), "r"(b[0]), "r"(b[1]));
}
__device__ __forceinline__ void ldsm_x4(uint32_t* r, uint32_t addr) {
    asm volatile("ldmatrix.sync.aligned.m8n8.x4.shared.b16 {%0,%1,%2,%3}, [%4];"
        : "=r"(r[0]), "=r"(r[1]), "=r"(r[2]), "=r"(r[3]) : "r"(addr));
}
__device__ __forceinline__ uint32_t smem_u32(const void* p) {
    uint32_t a;
    asm("{ .reg .u64 t; cvta.to.shared.u64 t, %1; cvt.u32.u64 %0, t; }" : "=r"(a) : "l"(p));
    return a;
}
__device__ __forceinline__ void bsplit(float w, __nv_bfloat16& hi, __nv_bfloat16& lo) {
    hi = __float2bfloat16(w);
    lo = __float2bfloat16(w - __bfloat162float(hi));
}
__device__ __forceinline__ int ld_acq(const int* p) {
    int v; asm volatile("ld.acquire.gpu.global.b32 %0, [%1];" : "=r"(v) : "l"(p)); return v;
}
__device__ __forceinline__ void red_add_release(int* p, int v) {
    asm volatile("red.release.gpu.global.add.s32 [%0], %1;" :: "l"(p), "r"(v) : "memory");
}
__device__ __forceinline__ void cp16(uint32_t s, const void* g) {
    asm volatile("cp.async.cg.shared.global [%0], [%1], 16;" :: "r"(s), "l"(g));
}
#define CP_COMMIT() asm volatile("cp.async.commit_group;" ::: "memory")
#define CP_WAIT(n)  asm volatile("cp.async.wait_group %0;" :: "n"(n) : "memory")

__global__ void reset_kernel()
{
    if (threadIdx.x < 4) g_cnt[threadIdx.x * 32] = 0;
}

// =====================================================================
// tf32 tensor-core GEMM body (software-pipelined k-slabs).
// =====================================================================
__device__ __forceinline__ void gemm_body(
    const float* __restrict__ A, const float* __restrict__ W,
    const float* __restrict__ b1, const float* __restrict__ b2,
    float* __restrict__ C, int N, int K,
    uint32_t (*As)[136], uint32_t (*Ws)[136])
{
    const int tid = threadIdx.x;
    const int lane = tid & 31, warp = tid >> 5;
    const int wm = (warp >> 2) * 64;
    const int wnn = (warp & 3) * 32;
    const int tig = lane & 3, grp = lane >> 2;

    const int n0 = blockIdx.x * 128, m0 = blockIdx.y * 128;
    const int lr = tid >> 1;
    const int kq = (tid & 1) * 8;

    float c[4][4][4];
#pragma unroll
    for (int mi = 0; mi < 4; mi++)
#pragma unroll
        for (int ni = 0; ni < 4; ni++)
#pragma unroll
            for (int j = 0; j < 4; j++) c[mi][ni][j] = 0.f;

    const float* Ap = A + (size_t)(m0 + lr) * K + kq;
    const float* Wp = W + (size_t)(n0 + lr) * K + kq;

    float4 av0 = *(const float4*)(Ap);
    float4 av1 = *(const float4*)(Ap + 4);
    float4 wv0 = *(const float4*)(Wp);
    float4 wv1 = *(const float4*)(Wp + 4);

    for (int k0 = 0; k0 < K; k0 += 16) {
        As[kq+0][lr] = f2tf32(av0.x); As[kq+1][lr] = f2tf32(av0.y);
        As[kq+2][lr] = f2tf32(av0.z); As[kq+3][lr] = f2tf32(av0.w);
        As[kq+4][lr] = f2tf32(av1.x); As[kq+5][lr] = f2tf32(av1.y);
        As[kq+6][lr] = f2tf32(av1.z); As[kq+7][lr] = f2tf32(av1.w);
        Ws[kq+0][lr] = f2tf32(wv0.x); Ws[kq+1][lr] = f2tf32(wv0.y);
        Ws[kq+2][lr] = f2tf32(wv0.z); Ws[kq+3][lr] = f2tf32(wv0.w);
        Ws[kq+4][lr] = f2tf32(wv1.x); Ws[kq+5][lr] = f2tf32(wv1.y);
        Ws[kq+6][lr] = f2tf32(wv1.z); Ws[kq+7][lr] = f2tf32(wv1.w);
        __syncthreads();

        if (k0 + 16 < K) {
            av0 = *(const float4*)(Ap + k0 + 16);
            av1 = *(const float4*)(Ap + k0 + 20);
            wv0 = *(const float4*)(Wp + k0 + 16);
            wv1 = *(const float4*)(Wp + k0 + 20);
        }

#pragma unroll
        for (int ks = 0; ks < 16; ks += 8) {
            uint32_t a[4][4], b[4][2];
#pragma unroll
            for (int mi = 0; mi < 4; mi++) {
                const int rb = wm + mi * 16 + grp;
                a[mi][0] = As[ks + tig][rb];
                a[mi][1] = As[ks + tig][rb + 8];
                a[mi][2] = As[ks + tig + 4][rb];
                a[mi][3] = As[ks + tig + 4][rb + 8];
            }
#pragma unroll
            for (int ni = 0; ni < 4; ni++) {
                const int nb = wnn + ni * 8 + grp;
                b[ni][0] = Ws[ks + tig][nb];
                b[ni][1] = Ws[ks + tig + 4][nb];
            }
#pragma unroll
            for (int mi = 0; mi < 4; mi++)
#pragma unroll
                for (int ni = 0; ni < 4; ni++)
                    mma_tf32(c[mi][ni], a[mi], b[ni]);
        }
        __syncthreads();
    }

#pragma unroll
    for (int ni = 0; ni < 4; ni++) {
        const int col = n0 + wnn + ni * 8 + tig * 2;
        float bias0 = b1[col], bias1 = b1[col + 1];
        if (b2) { bias0 += b2[col]; bias1 += b2[col + 1]; }
#pragma unroll
        for (int mi = 0; mi < 4; mi++) {
            const int row = m0 + wm + mi * 16 + grp;
            C[(size_t)row * N + col]           = c[mi][ni][0] + bias0;
            C[(size_t)row * N + col + 1]       = c[mi][ni][1] + bias1;
            C[(size_t)(row + 8) * N + col]     = c[mi][ni][2] + bias0;
            C[(size_t)(row + 8) * N + col + 1] = c[mi][ni][3] + bias1;
        }
    }
}

__global__ void __launch_bounds__(256)
mma_gemm_nt(const float* __restrict__ A, const float* __restrict__ W,
            const float* __restrict__ b1, const float* __restrict__ b2,
            float* __restrict__ C, int N, int K)
{
    __shared__ uint32_t As[16][136];
    __shared__ uint32_t Ws[16][136];
    gemm_body(A, W, b1, b2, C, N, K, As, Ws);
}

__global__ void __launch_bounds__(256)
mma_gemm_qkv(const float* __restrict__ A,
             const float* __restrict__ Wq, const float* __restrict__ Wk, const float* __restrict__ Wv,
             const float* __restrict__ bq, const float* __restrict__ bk, const float* __restrict__ bv,
             float* __restrict__ Oq, float* __restrict__ Ok, float* __restrict__ Ov)
{
    __shared__ uint32_t As[16][136];
    __shared__ uint32_t Ws[16][136];
    const int z = blockIdx.z;
    const float* W = (z == 0) ? Wq : (z == 1) ? Wk : Wv;
    const float* b = (z == 0) ? bq : (z == 1) ? bk : bv;
    float* O       = (z == 0) ? Oq : (z == 1) ? Ok : Ov;
    gemm_body(A, W, b, nullptr, O, HH, HH, As, Ws);
}

// =====================================================================
// Persistent LSTM: R8 barrier/staging + zero-redundancy warp-k-split MMA.
// Warp w: khalf=w&1, kwarp=w>>1 -> 8 ktiles at k = khalf*512 + kwarp*128.
// Each warp computes ALL 32 gate rows x 16 batches for its 8 ktiles;
// 8 partial planes reduced in the pointwise step.
// =====================================================================
__global__ void __launch_bounds__(256, 1)
lstm_kernel(const float* __restrict__ Whh)
{
    extern __shared__ char smraw[];
    __nv_bfloat16* Whi = (__nv_bfloat16*)smraw;          // [32][WSTRIDE]
    __nv_bfloat16* Wlo = Whi + 32 * WSTRIDE;
    __nv_bfloat16* hhi = Wlo + 32 * WSTRIDE;             // [16][WSTRIDE]
    __nv_bfloat16* hlo = hhi + 16 * WSTRIDE;
    float* gbuf = (float*)(hlo + 16 * WSTRIDE);          // [8][16][36]
    float* cst  = gbuf + 8 * 16 * 36;                    // [128]

    const int tid = threadIdx.x;
    const int cta = blockIdx.x;
    const int lane = tid & 31, warp = tid >> 5;
    const int grp = lane >> 2, tig = lane & 3;
    const int khalf = warp & 1;
    const int kwarp = warp >> 1;                         // 0..3

    // one-time: split W_hh slice into bf16 hi/lo in SMEM
    for (int i = tid; i < 32 * 1024; i += 256) {
        const int r = i >> 10, k = i & 1023;
        const int jrow = (r >> 3) * 1024 + cta * UPC + (r & 7);
        __nv_bfloat16 hi, lo;
        bsplit(Whh[(size_t)jrow * HH + k], hi, lo);
        Whi[r * WSTRIDE + k] = hi;
        Wlo[r * WSTRIDE + k] = lo;
    }
    if (tid < 128) cst[tid] = 0.f;
    __syncthreads();

    // per-warp k-chunk addressing (128 bf16 each)
    const uint32_t s_hhi = smem_u32(hhi), s_hlo = smem_u32(hlo);
    const uint32_t s_whi = smem_u32(Whi), s_wlo = smem_u32(Wlo);
    const uint32_t koffB = (uint32_t)(khalf * 1024 + kwarp * 256);

    // A (h): 16 batches x 16k per ktile
    const uint32_t ahi0 = s_hhi + (lane & 15) * (WSTRIDE * 2) + (lane >> 4) * 16 + koffB;
    const uint32_t alo0 = s_hlo + (lane & 15) * (WSTRIDE * 2) + (lane >> 4) * 16 + koffB;
    // B (W rows): two x4 cover rows 0-15 and 16-31 (hi and lo separately)
    const uint32_t brow = (uint32_t)(lane & 7) + ((lane >> 4) << 3);   // 0..15
    const uint32_t bcol = ((lane >> 3) & 1) * 16;
    const uint32_t bhiA = s_whi + brow * (WSTRIDE * 2) + bcol + koffB;
    const uint32_t bhiB = bhiA + 16 * (WSTRIDE * 2);
    const uint32_t bloA = s_wlo + brow * (WSTRIDE * 2) + bcol + koffB;
    const uint32_t bloB = bloA + 16 * (WSTRIDE * 2);

    const int su = tid & 7, sb = tid >> 3;               // pointwise map (tid<128)
    const int unit = cta * UPC + su;
    int* mycnt = &g_cnt[(cta & 3) * 32];
    float* pw = gbuf + warp * (16 * 36);

    // staging phase column bases (k-interleaved: kwarp<2 ready after 2 phases)
    const int phcol[4] = {0, 512, 256, 768};

    for (int t = 0; t < SS; t++) {
        // prefetch input-gate contributions (pointwise threads, before poll)
        float gt[4] = {0.f, 0.f, 0.f, 0.f};
        if (tid < 128) {
            const size_t goff = ((size_t)sb * SS + t) * HX4 + cta * UPC + su;
#pragma unroll
            for (int g = 0; g < 4; g++) gt[g] = g_gates[goff + g * 1024];
        }

        float c[4][4];
#pragma unroll
        for (int n = 0; n < 4; n++)
#pragma unroll
            for (int j = 0; j < 4; j++) c[n][j] = 0.f;

        if (t > 0) {
            // grid barrier (R8): warp0 lanes 0-3 poll the 4 group counters
            if (warp == 0 && lane < 4) {
                const int tgt = 32 * t;
                while (ld_acq(&g_cnt[lane * 32]) < tgt) { }
            }
            __syncthreads();

            // stage h_{t-1}: 4 k-interleaved phases via cp.async (R8)
            const __nv_bfloat16* shi = g_hhi[t & 1];
            const __nv_bfloat16* slo = g_hlo[t & 1];
#pragma unroll
            for (int ph = 0; ph < 4; ph++) {
#pragma unroll
                for (int j = 0; j < 2; j++) {
                    const int i = tid + j * 256;
                    const int row = i >> 5;
                    const int col = phcol[ph] + (i & 31) * 8;
                    cp16(s_hhi + row * (WSTRIDE * 2) + col * 2, shi + row * 1024 + col);
                    cp16(s_hlo + row * (WSTRIDE * 2) + col * 2, slo + row * 1024 + col);
                }
                CP_COMMIT();
            }

            CP_WAIT(2); __syncthreads();    // phases 0,1 ready (cols 0-255, 512-767)
            if (kwarp < 2) {
#pragma unroll
                for (int kt = 0; kt < 8; kt++) {
                    const uint32_t off = kt * 32;
                    uint32_t ah[4], al[4], bh1[4], bh2[4], bl1[4], bl2[4];
                    ldsm_x4(ah, ahi0 + off);
                    ldsm_x4(al, alo0 + off);
                    ldsm_x4(bh1, bhiA + off);
                    ldsm_x4(bh2, bhiB + off);
                    ldsm_x4(bl1, bloA + off);
                    ldsm_x4(bl2, bloB + off);
                    mma_bf16(c[0], ah, bh1);  mma_bf16(c[1], ah, bh1 + 2);
                    mma_bf16(c[2], ah, bh2);  mma_bf16(c[3], ah, bh2 + 2);
                    mma_bf16(c[0], al, bh1);  mma_bf16(c[1], al, bh1 + 2);
                    mma_bf16(c[2], al, bh2);  mma_bf16(c[3], al, bh2 + 2);
                    mma_bf16(c[0], ah, bl1);  mma_bf16(c[1], ah, bl1 + 2);
                    mma_bf16(c[2], ah, bl2);  mma_bf16(c[3], ah, bl2 + 2);
                }
            }
            CP_WAIT(0); __syncthreads();    // phases 2,3 ready
            if (kwarp >= 2) {
#pragma unroll
                for (int kt = 0; kt < 8; kt++) {
                    const uint32_t off = kt * 32;
                    uint32_t ah[4], al[4], bh1[4], bh2[4], bl1[4], bl2[4];
                    ldsm_x4(ah, ahi0 + off);
                    ldsm_x4(al, alo0 + off);
                    ldsm_x4(bh1, bhiA + off);
                    ldsm_x4(bh2, bhiB + off);
                    ldsm_x4(bl1, bloA + off);
                    ldsm_x4(bl2, bloB + off);
                    mma_bf16(c[0], ah, bh1);  mma_bf16(c[1], ah, bh1 + 2);
                    mma_bf16(c[2], ah, bh2);  mma_bf16(c[3], ah, bh2 + 2);
                    mma_bf16(c[0], al, bh1);  mma_bf16(c[1], al, bh1 + 2);
                    mma_bf16(c[2], al, bh2);  mma_bf16(c[3], al, bh2 + 2);
                    mma_bf16(c[0], ah, bl1);  mma_bf16(c[1], ah, bl1 + 2);
                    mma_bf16(c[2], ah, bl2);  mma_bf16(c[3], ah, bl2 + 2);
                }
            }
        }

        // store partials: plane[warp][batch][gate-row]
#pragma unroll
        for (int n = 0; n < 4; n++) {
            const int row = n * 8 + tig * 2;
            *(float2*)(pw + grp * 36 + row)       = make_float2(c[n][0], c[n][1]);
            *(float2*)(pw + (grp + 8) * 36 + row) = make_float2(c[n][2], c[n][3]);
        }
        __syncthreads();

        // pointwise LSTM cell (threads 0-127): sum 8 planes + gates
        float h = 0.f;
        if (tid < 128) {
            float iv = gt[0], fv = gt[1], gv = gt[2], ov = gt[3];
#pragma unroll
            for (int w = 0; w < 8; w++) {
                const float* p = gbuf + w * (16 * 36) + sb * 36 + su;
                iv += p[0];
                fv += p[8];
                gv += p[16];
                ov += p[24];
            }
            const float ig = 1.f / (1.f + expf(-iv));
            const float fg = 1.f / (1.f + expf(-fv));
            const float og = 1.f / (1.f + expf(-ov));
            const float cv = fg * cst[tid] + ig * tanhf(gv);
            cst[tid] = cv;
            h = og * tanhf(cv);
            __nv_bfloat16 hi, lo;
            bsplit(h, hi, lo);
            g_hhi[(t + 1) & 1][sb * HH + unit] = hi;
            g_hlo[(t + 1) & 1][sb * HH + unit] = lo;
        }
        __syncthreads();                          // h stores + gbuf reads done
        if (tid == 0) red_add_release(mycnt, 1);  // release-cumulative publish
        if (tid < 128)
            g_enc[((size_t)sb * SS + t) * HH + unit] = h;   // off critical path
    }
}

// ============ block reduction helper (256 threads) ============
__device__ __forceinline__ float blk_sum256(float v, float* red)
{
#pragma unroll
    for (int o = 16; o > 0; o >>= 1) v += __shfl_down_sync(0xffffffffu, v, o);
    const int tid = threadIdx.x;
    if ((tid & 31) == 0) red[tid >> 5] = v;
    __syncthreads();
    if (tid < 32) {
        float x = (tid < 8) ? red[tid] : 0.f;
#pragma unroll
        for (int o = 4; o > 0; o >>= 1) x += __shfl_down_sync(0xffffffffu, x, o);
        if (tid == 0) red[0] = x;
    }
    __syncthreads();
    const float s = red[0];
    __syncthreads();
    return s;
}

// ============ span mean-pool + LayerNorm ============
__global__ void pool_ln_kernel(const float* __restrict__ gamma, const float* __restrict__ beta,
                               const int* __restrict__ heads, const int* __restrict__ tails)
{
    __shared__ float red[32];
    const int span = blockIdx.x;
    const int tid = threadIdx.x;
    const int b = span >> 5;
    const int head = heads[span], tail = tails[span];

    float4 acc = make_float4(0.f, 0.f, 0.f, 0.f);
    for (int s = head + 1; s < tail; s++) {
        const float4 v = *(const float4*)(g_enc + ((size_t)b * SS + s) * HH + tid * 4);
        acc.x += v.x; acc.y += v.y; acc.z += v.z; acc.w += v.w;
    }
    const float invc = 1.f / (float)(tail - head - 1);
    acc.x *= invc; acc.y *= invc; acc.z *= invc; acc.w *= invc;

    const float mu = blk_sum256(acc.x + acc.y + acc.z + acc.w, red) * (1.f / HH);
    const float dx = acc.x - mu, dy = acc.y - mu, dz = acc.z - mu, dw = acc.w - mu;
    const float var = blk_sum256(dx*dx + dy*dy + dz*dz + dw*dw, red) * (1.f / HH);
    const float rstd = rsqrtf(var + 1e-7f);

    const int h = tid * 4;
    const float4 gm = *(const float4*)(gamma + h);
    const float4 bt = *(const float4*)(beta + h);
    float4 o = make_float4(dx*rstd*gm.x + bt.x, dy*rstd*gm.y + bt.y,
                           dz*rstd*gm.z + bt.z, dw*rstd*gm.w + bt.w);
    *(float4*)(g_pool + (size_t)span * HH + h) = o;
}

// ============ residual LayerNorm ============
__global__ void ln_res_kernel(const float* __restrict__ gamma, const float* __restrict__ beta)
{
    __shared__ float red[32];
    const int row = blockIdx.x;
    const int tid = threadIdx.x;
    const size_t off = (size_t)row * HH + tid * 4;

    float4 x = *(const float4*)(g_wo + off);
    const float4 p = *(const float4*)(g_pool + off);
    x.x += p.x; x.y += p.y; x.z += p.z; x.w += p.w;

    const float mu = blk_sum256(x.x + x.y + x.z + x.w, red) * (1.f / HH);
    const float dx = x.x - mu, dy = x.y - mu, dz = x.z - mu, dw = x.w - mu;
    const float var = blk_sum256(dx*dx + dy*dy + dz*dz + dw*dw, red) * (1.f / HH);
    const float rstd = rsqrtf(var + 1e-7f);

    const int h = tid * 4;
    const float4 gm = *(const float4*)(gamma + h);
    const float4 bt = *(const float4*)(beta + h);
    float4 o = make_float4(dx*rstd*gm.x + bt.x, dy*rstd*gm.y + bt.y,
                           dz*rstd*gm.z + bt.z, dw*rstd*gm.w + bt.w);
    *(float4*)(g_attn + off) = o;
}

// ============ span attention: one CTA per (b, head) ============
__global__ void attn_kernel(const int* __restrict__ mask)
{
    __shared__ float Qs[32][65], Ks[32][65], Vs[32][65];
    __shared__ float P[32][33];
    __shared__ int ms[32];

    const int bh = blockIdx.x;
    const int b = bh / NHEADS, hd = bh % NHEADS;
    const int tid = threadIdx.x;
    const size_t rowbase = (size_t)b * NSPAN;
    const int col0 = hd * DHEAD;

    for (int i = tid; i < NSPAN * DHEAD; i += 128) {
        const int n = i >> 6, d = i & 63;
        const size_t off = (rowbase + n) * HH + col0 + d;
        Qs[n][d] = g_q[off];
        Ks[n][d] = g_k[off];
        Vs[n][d] = g_v[off];
    }
    if (tid < 32) ms[tid] = mask[b * NSPAN + tid];
    __syncthreads();

    for (int i = tid; i < 1024; i += 128) {
        const int qi = i >> 5, kj = i & 31;
        float s = 0.f;
#pragma unroll
        for (int d = 0; d < 64; d++) s += Qs[qi][d] * Ks[kj][d];
        s *= 0.125f;
        P[qi][kj] = (ms[qi] && ms[kj]) ? s : -3.402823466e38f;
    }
    __syncthreads();

    if (tid < 32) {
        float mx = -3.402823466e38f;
#pragma unroll
        for (int j = 0; j < 32; j++) mx = fmaxf(mx, P[tid][j]);
        float sum = 0.f;
#pragma unroll
        for (int j = 0; j < 32; j++) { float e = expf(P[tid][j] - mx); P[tid][j] = e; sum += e; }
        const float inv = 1.f / sum;
#pragma unroll
        for (int j = 0; j < 32; j++) P[tid][j] = (ms[tid] && ms[j]) ? P[tid][j] * inv : 0.f;
    }
    __syncthreads();

    for (int i = tid; i < NSPAN * DHEAD; i += 128) {
        const int qi = i >> 6, d = i & 63;
        float s = 0.f;
#pragma unroll
        for (int j = 0; j < 32; j++) s += P[qi][j] * Vs[j][d];
        g_ctx[(rowbase + qi) * HH + col0 + d] = s;
    }
}

// ============ classifier: warp per row, N=5 ============
__global__ void __launch_bounds__(256)
clf_kernel(const float* __restrict__ W, const float* __restrict__ b, float* __restrict__ out)
{
    __shared__ float ws[NCLS * HH];
    const int tid = threadIdx.x;
    for (int i = tid; i < NCLS * HH; i += 256) ws[i] = W[i];
    __syncthreads();

    const int warp = tid >> 5, lane = tid & 31;
    const int row = blockIdx.x * 8 + warp;
    const float* a = g_attn + (size_t)row * HH;

    float acc[NCLS] = {0.f, 0.f, 0.f, 0.f, 0.f};
    for (int k = lane; k < HH; k += 32) {
        const float av = a[k];
#pragma unroll
        for (int c = 0; c < NCLS; c++) acc[c] += av * ws[c * HH + k];
    }
#pragma unroll
    for (int c = 0; c < NCLS; c++) {
#pragma unroll
        for (int o = 16; o > 0; o >>= 1) acc[c] += __shfl_down_sync(0xffffffffu, acc[c], o);
    }
    if (lane == 0) {
#pragma unroll
        for (int c = 0; c < NCLS; c++) out[(size_t)row * NCLS + c] = acc[c] + b[c];
    }
}

// ============ launch ============
extern "C" void kernel_launch(void* const* d_in, const int* in_sizes, int n_in,
                              void* d_out, int out_size)
{
    const float* enc_in  = (const float*)d_in[0];
    const float* W_ih    = (const float*)d_in[1];
    const float* W_hh    = (const float*)d_in[2];
    const float* b_ih    = (const float*)d_in[3];
    const float* b_hh    = (const float*)d_in[4];
    const float* ln_g    = (const float*)d_in[5];
    const float* ln_b    = (const float*)d_in[6];
    const float* Wq      = (const float*)d_in[7];
    const float* bq      = (const float*)d_in[8];
    const float* Wk      = (const float*)d_in[9];
    const float* bk      = (const float*)d_in[10];
    const float* Wv      = (const float*)d_in[11];
    const float* bv      = (const float*)d_in[12];
    const float* Wo      = (const float*)d_in[13];
    const float* bo      = (const float*)d_in[14];
    const float* aln_g   = (const float*)d_in[15];
    const float* aln_b   = (const float*)d_in[16];
    const float* clf_W   = (const float*)d_in[17];
    const float* clf_b   = (const float*)d_in[18];
    const int*   heads   = (const int*)d_in[19];
    const int*   tails   = (const int*)d_in[20];
    const int*   mask    = (const int*)d_in[21];
    float* out = (float*)d_out;

    float *gates, *pool, *q, *k, *v, *ctx, *wo_buf;
    cudaGetSymbolAddress((void**)&gates,  g_gates);
    cudaGetSymbolAddress((void**)&pool,   g_pool);
    cudaGetSymbolAddress((void**)&q,      g_q);
    cudaGetSymbolAddress((void**)&k,      g_k);
    cudaGetSymbolAddress((void**)&v,      g_v);
    cudaGetSymbolAddress((void**)&ctx,    g_ctx);
    cudaGetSymbolAddress((void**)&wo_buf, g_wo);

    // 0. reset barrier counters
    reset_kernel<<<1, 32>>>();

    // 1. gates = X @ W_ih^T + b_ih + b_hh   (tf32, pipelined)
    mma_gemm_nt<<<dim3(HX4 / 128, (BB * SS) / 128), 256>>>(
        enc_in, W_ih, b_ih, b_hh, gates, HX4, HH);

    // 2. persistent LSTM (warp-k-split, zero-redundancy LDSM)
    const int smem = (32 * WSTRIDE * 2 + 16 * WSTRIDE * 2) * (int)sizeof(__nv_bfloat16)
                   + (8 * 16 * 36 + 128) * (int)sizeof(float);
    cudaFuncSetAttribute(lstm_kernel, cudaFuncAttributeMaxDynamicSharedMemorySize, smem);
    lstm_kernel<<<NCTA, 256, smem>>>(W_hh);

    // 3. span pool + LN
    pool_ln_kernel<<<BB * NSPAN, 256>>>(ln_g, ln_b, heads, tails);

    // 4. fused QKV projections (tf32)
    mma_gemm_qkv<<<dim3(HH / 128, (BB * NSPAN) / 128, 3), 256>>>(
        pool, Wq, Wk, Wv, bq, bk, bv, q, k, v);

    // 5. attention
    attn_kernel<<<BB * NHEADS, 128>>>(mask);

    // 6. output projection (tf32)
    mma_gemm_nt<<<dim3(HH / 128, (BB * NSPAN) / 128), 256>>>(ctx, Wo, bo, nullptr, wo_buf, HH, HH);

    // 7. residual LN
    ln_res_kernel<<<BB * NSPAN, 256>>>(aln_g, aln_b);

    // 8. classifier -> d_out [B,NS,L]
    clf_kernel<<<(BB * NSPAN) / 8, 256>>>(clf_W, clf_b, out);
}

// round 15
// speedup vs baseline: 1.7225x; 1.0072x over previous
#include <cuda_runtime.h>
#include <cuda_bf16.h>
#include <math.h>
#include <stdint.h>

#define BB      16
#define SS      1024
#define HH      1024
#define HX4     4096
#define NSPAN   32
#define NHEADS  16
#define DHEAD   64
#define NCLS    5
#define NCTA    128
#define UPC     8
#define WSTRIDE 1032   // padded bf16 row stride -> conflict-free ldmatrix

// ---------------- device scratch ----------------
__device__ float g_gates[(size_t)BB * SS * HX4];   // [b][s][4H]
__device__ float g_enc  [(size_t)BB * SS * HH];
__device__ __nv_bfloat16 g_hhi[2][BB * HH];
__device__ __nv_bfloat16 g_hlo[2][BB * HH];
__device__ int g_cnt[4 * 32];                      // 4 group counters, 128B apart
__device__ float g_pool [BB * NSPAN * HH];
__device__ float g_q    [BB * NSPAN * HH];
__device__ float g_k    [BB * NSPAN * HH];
__device__ float g_v    [BB * NSPAN * HH];
__device__ float g_ctx  [BB * NSPAN * HH];
__device__ float g_wo   [BB * NSPAN * HH];
__device__ float g_attn [BB * NSPAN * HH];

// ---------------- asm helpers ----------------
__device__ __forceinline__ uint32_t f2tf32(float x) {
    uint32_t r; asm("cvt.rna.tf32.f32 %0, %1;" : "=r"(r) : "f"(x)); return r;
}
__device__ __forceinline__ void mma_tf32(float* c, const uint32_t* a, const uint32_t* b) {
    asm volatile("mma.sync.aligned.m16n8k8.row.col.f32.tf32.tf32.f32 "
        "{%0,%1,%2,%3}, {%4,%5,%6,%7}, {%8,%9}, {%0,%1,%2,%3};"
        : "+f"(c[0]), "+f"(c[1]), "+f"(c[2]), "+f"(c[3])
        : "r"(a[0]), "r"(a[1]), "r"(a[2]), "r"(a[3]), "r"(b[0]), "r"(b[1]));
}
__device__ __forceinline__ void mma_bf16(float* c, const uint32_t* a, const uint32_t* b) {
    asm volatile("mma.sync.aligned.m16n8k16.row.col.f32.bf16.bf16.f32 "
        "{%0,%1,%2,%3}, {%4,%5,%6,%7}, {%8,%9}, {%0,%1,%2,%3};"
        : "+f"(c[0]), "+f"(c[1]), "+f"(c[2]), "+f"(c[3])
        : "r"(a[0]), "r"(a[1]), "r"(a[2]), "r"(a[3]), "r"(b[0]), "r"(b[1]));
}
__device__ __forceinline__ void ldsm_x4(uint32_t* r, uint32_t addr) {
    asm volatile("ldmatrix.sync.aligned.m8n8.x4.shared.b16 {%0,%1,%2,%3}, [%4];"
        : "=r"(r[0]), "=r"(r[1]), "=r"(r[2]), "=r"(r[3]) : "r"(addr));
}
__device__ __forceinline__ uint32_t smem_u32(const void* p) {
    uint32_t a;
    asm("{ .reg .u64 t; cvta.to.shared.u64 t, %1; cvt.u32.u64 %0, t; }" : "=r"(a) : "l"(p));
    return a;
}
__device__ __forceinline__ void bsplit(float w, __nv_bfloat16& hi, __nv_bfloat16& lo) {
    hi = __float2bfloat16(w);
    lo = __float2bfloat16(w - __bfloat162float(hi));
}
__device__ __forceinline__ int ld_acq(const int* p) {
    int v; asm volatile("ld.acquire.gpu.global.b32 %0, [%1];" : "=r"(v) : "l"(p)); return v;
}
__device__ __forceinline__ void red_add_release(int* p, int v) {
    asm volatile("red.release.gpu.global.add.s32 [%0], %1;" :: "l"(p), "r"(v) : "memory");
}
__device__ __forceinline__ void cp16(uint32_t s, const void* g) {
    asm volatile("cp.async.cg.shared.global [%0], [%1], 16;" :: "r"(s), "l"(g));
}
#define CP_COMMIT() asm volatile("cp.async.commit_group;" ::: "memory")
#define CP_WAIT(n)  asm volatile("cp.async.wait_group %0;" :: "n"(n) : "memory")

__global__ void reset_kernel()
{
    if (threadIdx.x < 4) g_cnt[threadIdx.x * 32] = 0;
}

// =====================================================================
// tf32 tensor-core GEMM body (software-pipelined k-slabs).
// =====================================================================
__device__ __forceinline__ void gemm_body(
    const float* __restrict__ A, const float* __restrict__ W,
    const float* __restrict__ b1, const float* __restrict__ b2,
    float* __restrict__ C, int N, int K,
    uint32_t (*As)[136], uint32_t (*Ws)[136])
{
    const int tid = threadIdx.x;
    const int lane = tid & 31, warp = tid >> 5;
    const int wm = (warp >> 2) * 64;
    const int wnn = (warp & 3) * 32;
    const int tig = lane & 3, grp = lane >> 2;

    const int n0 = blockIdx.x * 128, m0 = blockIdx.y * 128;
    const int lr = tid >> 1;
    const int kq = (tid & 1) * 8;

    float c[4][4][4];
#pragma unroll
    for (int mi = 0; mi < 4; mi++)
#pragma unroll
        for (int ni = 0; ni < 4; ni++)
#pragma unroll
            for (int j = 0; j < 4; j++) c[mi][ni][j] = 0.f;

    const float* Ap = A + (size_t)(m0 + lr) * K + kq;
    const float* Wp = W + (size_t)(n0 + lr) * K + kq;

    float4 av0 = *(const float4*)(Ap);
    float4 av1 = *(const float4*)(Ap + 4);
    float4 wv0 = *(const float4*)(Wp);
    float4 wv1 = *(const float4*)(Wp + 4);

    for (int k0 = 0; k0 < K; k0 += 16) {
        As[kq+0][lr] = f2tf32(av0.x); As[kq+1][lr] = f2tf32(av0.y);
        As[kq+2][lr] = f2tf32(av0.z); As[kq+3][lr] = f2tf32(av0.w);
        As[kq+4][lr] = f2tf32(av1.x); As[kq+5][lr] = f2tf32(av1.y);
        As[kq+6][lr] = f2tf32(av1.z); As[kq+7][lr] = f2tf32(av1.w);
        Ws[kq+0][lr] = f2tf32(wv0.x); Ws[kq+1][lr] = f2tf32(wv0.y);
        Ws[kq+2][lr] = f2tf32(wv0.z); Ws[kq+3][lr] = f2tf32(wv0.w);
        Ws[kq+4][lr] = f2tf32(wv1.x); Ws[kq+5][lr] = f2tf32(wv1.y);
        Ws[kq+6][lr] = f2tf32(wv1.z); Ws[kq+7][lr] = f2tf32(wv1.w);
        __syncthreads();

        if (k0 + 16 < K) {
            av0 = *(const float4*)(Ap + k0 + 16);
            av1 = *(const float4*)(Ap + k0 + 20);
            wv0 = *(const float4*)(Wp + k0 + 16);
            wv1 = *(const float4*)(Wp + k0 + 20);
        }

#pragma unroll
        for (int ks = 0; ks < 16; ks += 8) {
            uint32_t a[4][4], b[4][2];
#pragma unroll
            for (int mi = 0; mi < 4; mi++) {
                const int rb = wm + mi * 16 + grp;
                a[mi][0] = As[ks + tig][rb];
                a[mi][1] = As[ks + tig][rb + 8];
                a[mi][2] = As[ks + tig + 4][rb];
                a[mi][3] = As[ks + tig + 4][rb + 8];
            }
#pragma unroll
            for (int ni = 0; ni < 4; ni++) {
                const int nb = wnn + ni * 8 + grp;
                b[ni][0] = Ws[ks + tig][nb];
                b[ni][1] = Ws[ks + tig + 4][nb];
            }
#pragma unroll
            for (int mi = 0; mi < 4; mi++)
#pragma unroll
                for (int ni = 0; ni < 4; ni++)
                    mma_tf32(c[mi][ni], a[mi], b[ni]);
        }
        __syncthreads();
    }

#pragma unroll
    for (int ni = 0; ni < 4; ni++) {
        const int col = n0 + wnn + ni * 8 + tig * 2;
        float bias0 = b1[col], bias1 = b1[col + 1];
        if (b2) { bias0 += b2[col]; bias1 += b2[col + 1]; }
#pragma unroll
        for (int mi = 0; mi < 4; mi++) {
            const int row = m0 + wm + mi * 16 + grp;
            C[(size_t)row * N + col]           = c[mi][ni][0] + bias0;
            C[(size_t)row * N + col + 1]       = c[mi][ni][1] + bias1;
            C[(size_t)(row + 8) * N + col]     = c[mi][ni][2] + bias0;
            C[(size_t)(row + 8) * N + col + 1] = c[mi][ni][3] + bias1;
        }
    }
}

__global__ void __launch_bounds__(256)
mma_gemm_nt(const float* __restrict__ A, const float* __restrict__ W,
            const float* __restrict__ b1, const float* __restrict__ b2,
            float* __restrict__ C, int N, int K)
{
    __shared__ uint32_t As[16][136];
    __shared__ uint32_t Ws[16][136];
    gemm_body(A, W, b1, b2, C, N, K, As, Ws);
}

__global__ void __launch_bounds__(256)
mma_gemm_qkv(const float* __restrict__ A,
             const float* __restrict__ Wq, const float* __restrict__ Wk, const float* __restrict__ Wv,
             const float* __restrict__ bq, const float* __restrict__ bk, const float* __restrict__ bv,
             float* __restrict__ Oq, float* __restrict__ Ok, float* __restrict__ Ov)
{
    __shared__ uint32_t As[16][136];
    __shared__ uint32_t Ws[16][136];
    const int z = blockIdx.z;
    const float* W = (z == 0) ? Wq : (z == 1) ? Wk : Wv;
    const float* b = (z == 0) ? bq : (z == 1) ? bk : bv;
    float* O       = (z == 0) ? Oq : (z == 1) ? Ok : Ov;
    gemm_body(A, W, b, nullptr, O, HH, HH, As, Ws);
}

// =====================================================================
// Persistent LSTM: R14 + balanced 2-phase MMA.
// Warp w owns 8 ktiles split 4+4: early cols [w*64, w*64+64) (phase A),
// late cols [512+w*64, +64) (phase B). All 8 warps MMA in both phases.
// Partials -> 8 SMEM planes, reduced in the pointwise step.
// =====================================================================
__global__ void __launch_bounds__(256, 1)
lstm_kernel(const float* __restrict__ Whh)
{
    extern __shared__ char smraw[];
    __nv_bfloat16* Whi = (__nv_bfloat16*)smraw;          // [32][WSTRIDE]
    __nv_bfloat16* Wlo = Whi + 32 * WSTRIDE;
    __nv_bfloat16* hhi = Wlo + 32 * WSTRIDE;             // [16][WSTRIDE]
    __nv_bfloat16* hlo = hhi + 16 * WSTRIDE;
    float* gbuf = (float*)(hlo + 16 * WSTRIDE);          // [8][16][36]
    float* cst  = gbuf + 8 * 16 * 36;                    // [128]

    const int tid = threadIdx.x;
    const int cta = blockIdx.x;
    const int lane = tid & 31, warp = tid >> 5;
    const int grp = lane >> 2, tig = lane & 3;

    // one-time: split W_hh slice into bf16 hi/lo in SMEM
    for (int i = tid; i < 32 * 1024; i += 256) {
        const int r = i >> 10, k = i & 1023;
        const int jrow = (r >> 3) * 1024 + cta * UPC + (r & 7);
        __nv_bfloat16 hi, lo;
        bsplit(Whh[(size_t)jrow * HH + k], hi, lo);
        Whi[r * WSTRIDE + k] = hi;
        Wlo[r * WSTRIDE + k] = lo;
    }
    if (tid < 128) cst[tid] = 0.f;
    __syncthreads();

    // per-warp k-chunk addressing: early chunk at cols [w*64), late at +512
    const uint32_t s_hhi = smem_u32(hhi), s_hlo = smem_u32(hlo);
    const uint32_t s_whi = smem_u32(Whi), s_wlo = smem_u32(Wlo);
    const uint32_t koffA = (uint32_t)warp * 128;          // 64 bf16 = 128 B
    const uint32_t koffB2 = koffA + 1024;                 // +512 cols

    // A (h): 16 batches x 16k per ktile
    const uint32_t aBase = (lane & 15) * (WSTRIDE * 2) + (lane >> 4) * 16;
    const uint32_t ahiA = s_hhi + aBase + koffA;
    const uint32_t aloA = s_hlo + aBase + koffA;
    const uint32_t ahiB = s_hhi + aBase + koffB2;
    const uint32_t aloB = s_hlo + aBase + koffB2;
    // B (W rows): two x4 cover rows 0-15 and 16-31 (hi and lo separately)
    const uint32_t brow = (uint32_t)(lane & 7) + ((lane >> 4) << 3);   // 0..15
    const uint32_t bcol = ((lane >> 3) & 1) * 16;
    const uint32_t bB = brow * (WSTRIDE * 2) + bcol;
    const uint32_t bhiA1 = s_whi + bB + koffA,  bhiA2 = bhiA1 + 16 * (WSTRIDE * 2);
    const uint32_t bloA1 = s_wlo + bB + koffA,  bloA2 = bloA1 + 16 * (WSTRIDE * 2);
    const uint32_t bhiB1 = s_whi + bB + koffB2, bhiB2 = bhiB1 + 16 * (WSTRIDE * 2);
    const uint32_t bloB1 = s_wlo + bB + koffB2, bloB2 = bloB1 + 16 * (WSTRIDE * 2);

    const int su = tid & 7, sb = tid >> 3;               // pointwise map (tid<128)
    const int unit = cta * UPC + su;
    int* mycnt = &g_cnt[(cta & 3) * 32];
    float* pw = gbuf + warp * (16 * 36);

    for (int t = 0; t < SS; t++) {
        // prefetch input-gate contributions (pointwise threads, before poll)
        float gt[4] = {0.f, 0.f, 0.f, 0.f};
        if (tid < 128) {
            const size_t goff = ((size_t)sb * SS + t) * HX4 + cta * UPC + su;
#pragma unroll
            for (int g = 0; g < 4; g++) gt[g] = g_gates[goff + g * 1024];
        }

        float c[4][4];
#pragma unroll
        for (int n = 0; n < 4; n++)
#pragma unroll
            for (int j = 0; j < 4; j++) c[n][j] = 0.f;

        if (t > 0) {
            // grid barrier: warp0 lanes 0-3 poll the 4 group counters
            if (warp == 0 && lane < 4) {
                const int tgt = 32 * t;
                while (ld_acq(&g_cnt[lane * 32]) < tgt) { }
            }
            __syncthreads();

            // stage h_{t-1}: 2 phases (cols 0-511, then 512-1023) via cp.async
            const __nv_bfloat16* shi = g_hhi[t & 1];
            const __nv_bfloat16* slo = g_hlo[t & 1];
#pragma unroll
            for (int ph = 0; ph < 2; ph++) {
#pragma unroll
                for (int j = 0; j < 4; j++) {
                    const int i = tid + j * 256;          // 0..1023
                    const int row = i >> 6;               // 0..15
                    const int col = ph * 512 + (i & 63) * 8;
                    cp16(s_hhi + row * (WSTRIDE * 2) + col * 2, shi + row * 1024 + col);
                    cp16(s_hlo + row * (WSTRIDE * 2) + col * 2, slo + row * 1024 + col);
                }
                CP_COMMIT();
            }

            // phase A: every warp MMAs its early 4 ktiles
            CP_WAIT(1); __syncthreads();
#pragma unroll
            for (int kt = 0; kt < 4; kt++) {
                const uint32_t off = kt * 32;
                uint32_t ah[4], al[4], bh1[4], bh2[4], bl1[4], bl2[4];
                ldsm_x4(ah, ahiA + off);
                ldsm_x4(al, aloA + off);
                ldsm_x4(bh1, bhiA1 + off);
                ldsm_x4(bh2, bhiA2 + off);
                ldsm_x4(bl1, bloA1 + off);
                ldsm_x4(bl2, bloA2 + off);
                mma_bf16(c[0], ah, bh1);  mma_bf16(c[1], ah, bh1 + 2);
                mma_bf16(c[2], ah, bh2);  mma_bf16(c[3], ah, bh2 + 2);
                mma_bf16(c[0], al, bh1);  mma_bf16(c[1], al, bh1 + 2);
                mma_bf16(c[2], al, bh2);  mma_bf16(c[3], al, bh2 + 2);
                mma_bf16(c[0], ah, bl1);  mma_bf16(c[1], ah, bl1 + 2);
                mma_bf16(c[2], ah, bl2);  mma_bf16(c[3], ah, bl2 + 2);
            }
            // phase B: every warp MMAs its late 4 ktiles
            CP_WAIT(0); __syncthreads();
#pragma unroll
            for (int kt = 0; kt < 4; kt++) {
                const uint32_t off = kt * 32;
                uint32_t ah[4], al[4], bh1[4], bh2[4], bl1[4], bl2[4];
                ldsm_x4(ah, ahiB + off);
                ldsm_x4(al, aloB + off);
                ldsm_x4(bh1, bhiB1 + off);
                ldsm_x4(bh2, bhiB2 + off);
                ldsm_x4(bl1, bloB1 + off);
                ldsm_x4(bl2, bloB2 + off);
                mma_bf16(c[0], ah, bh1);  mma_bf16(c[1], ah, bh1 + 2);
                mma_bf16(c[2], ah, bh2);  mma_bf16(c[3], ah, bh2 + 2);
                mma_bf16(c[0], al, bh1);  mma_bf16(c[1], al, bh1 + 2);
                mma_bf16(c[2], al, bh2);  mma_bf16(c[3], al, bh2 + 2);
                mma_bf16(c[0], ah, bl1);  mma_bf16(c[1], ah, bl1 + 2);
                mma_bf16(c[2], ah, bl2);  mma_bf16(c[3], ah, bl2 + 2);
            }
        }

        // store partials: plane[warp][batch][gate-row]
#pragma unroll
        for (int n = 0; n < 4; n++) {
            const int row = n * 8 + tig * 2;
            *(float2*)(pw + grp * 36 + row)       = make_float2(c[n][0], c[n][1]);
            *(float2*)(pw + (grp + 8) * 36 + row) = make_float2(c[n][2], c[n][3]);
        }
        __syncthreads();

        // pointwise LSTM cell (threads 0-127): sum 8 planes + gates
        float h = 0.f;
        if (tid < 128) {
            float iv = gt[0], fv = gt[1], gv = gt[2], ov = gt[3];
#pragma unroll
            for (int w = 0; w < 8; w++) {
                const float* p = gbuf + w * (16 * 36) + sb * 36 + su;
                iv += p[0];
                fv += p[8];
                gv += p[16];
                ov += p[24];
            }
            const float ig = 1.f / (1.f + expf(-iv));
            const float fg = 1.f / (1.f + expf(-fv));
            const float og = 1.f / (1.f + expf(-ov));
            const float cv = fg * cst[tid] + ig * tanhf(gv);
            cst[tid] = cv;
            h = og * tanhf(cv);
            __nv_bfloat16 hi, lo;
            bsplit(h, hi, lo);
            g_hhi[(t + 1) & 1][sb * HH + unit] = hi;
            g_hlo[(t + 1) & 1][sb * HH + unit] = lo;
        }
        __syncthreads();                          // h stores + gbuf reads done
        if (tid == 0) red_add_release(mycnt, 1);  // release-cumulative publish
        if (tid < 128)
            g_enc[((size_t)sb * SS + t) * HH + unit] = h;   // off critical path
    }
}

// ============ block reduction helper (256 threads) ============
__device__ __forceinline__ float blk_sum256(float v, float* red)
{
#pragma unroll
    for (int o = 16; o > 0; o >>= 1) v += __shfl_down_sync(0xffffffffu, v, o);
    const int tid = threadIdx.x;
    if ((tid & 31) == 0) red[tid >> 5] = v;
    __syncthreads();
    if (tid < 32) {
        float x = (tid < 8) ? red[tid] : 0.f;
#pragma unroll
        for (int o = 4; o > 0; o >>= 1) x += __shfl_down_sync(0xffffffffu, x, o);
        if (tid == 0) red[0] = x;
    }
    __syncthreads();
    const float s = red[0];
    __syncthreads();
    return s;
}

// ============ span mean-pool + LayerNorm ============
__global__ void pool_ln_kernel(const float* __restrict__ gamma, const float* __restrict__ beta,
                               const int* __restrict__ heads, const int* __restrict__ tails)
{
    __shared__ float red[32];
    const int span = blockIdx.x;
    const int tid = threadIdx.x;
    const int b = span >> 5;
    const int head = heads[span], tail = tails[span];

    float4 acc = make_float4(0.f, 0.f, 0.f, 0.f);
    for (int s = head + 1; s < tail; s++) {
        const float4 v = *(const float4*)(g_enc + ((size_t)b * SS + s) * HH + tid * 4);
        acc.x += v.x; acc.y += v.y; acc.z += v.z; acc.w += v.w;
    }
    const float invc = 1.f / (float)(tail - head - 1);
    acc.x *= invc; acc.y *= invc; acc.z *= invc; acc.w *= invc;

    const float mu = blk_sum256(acc.x + acc.y + acc.z + acc.w, red) * (1.f / HH);
    const float dx = acc.x - mu, dy = acc.y - mu, dz = acc.z - mu, dw = acc.w - mu;
    const float var = blk_sum256(dx*dx + dy*dy + dz*dz + dw*dw, red) * (1.f / HH);
    const float rstd = rsqrtf(var + 1e-7f);

    const int h = tid * 4;
    const float4 gm = *(const float4*)(gamma + h);
    const float4 bt = *(const float4*)(beta + h);
    float4 o = make_float4(dx*rstd*gm.x + bt.x, dy*rstd*gm.y + bt.y,
                           dz*rstd*gm.z + bt.z, dw*rstd*gm.w + bt.w);
    *(float4*)(g_pool + (size_t)span * HH + h) = o;
}

// ============ residual LayerNorm ============
__global__ void ln_res_kernel(const float* __restrict__ gamma, const float* __restrict__ beta)
{
    __shared__ float red[32];
    const int row = blockIdx.x;
    const int tid = threadIdx.x;
    const size_t off = (size_t)row * HH + tid * 4;

    float4 x = *(const float4*)(g_wo + off);
    const float4 p = *(const float4*)(g_pool + off);
    x.x += p.x; x.y += p.y; x.z += p.z; x.w += p.w;

    const float mu = blk_sum256(x.x + x.y + x.z + x.w, red) * (1.f / HH);
    const float dx = x.x - mu, dy = x.y - mu, dz = x.z - mu, dw = x.w - mu;
    const float var = blk_sum256(dx*dx + dy*dy + dz*dz + dw*dw, red) * (1.f / HH);
    const float rstd = rsqrtf(var + 1e-7f);

    const int h = tid * 4;
    const float4 gm = *(const float4*)(gamma + h);
    const float4 bt = *(const float4*)(beta + h);
    float4 o = make_float4(dx*rstd*gm.x + bt.x, dy*rstd*gm.y + bt.y,
                           dz*rstd*gm.z + bt.z, dw*rstd*gm.w + bt.w);
    *(float4*)(g_attn + off) = o;
}

// ============ span attention: one CTA per (b, head) ============
__global__ void attn_kernel(const int* __restrict__ mask)
{
    __shared__ float Qs[32][65], Ks[32][65], Vs[32][65];
    __shared__ float P[32][33];
    __shared__ int ms[32];

    const int bh = blockIdx.x;
    const int b = bh / NHEADS, hd = bh % NHEADS;
    const int tid = threadIdx.x;
    const size_t rowbase = (size_t)b * NSPAN;
    const int col0 = hd * DHEAD;

    for (int i = tid; i < NSPAN * DHEAD; i += 128) {
        const int n = i >> 6, d = i & 63;
        const size_t off = (rowbase + n) * HH + col0 + d;
        Qs[n][d] = g_q[off];
        Ks[n][d] = g_k[off];
        Vs[n][d] = g_v[off];
    }
    if (tid < 32) ms[tid] = mask[b * NSPAN + tid];
    __syncthreads();

    for (int i = tid; i < 1024; i += 128) {
        const int qi = i >> 5, kj = i & 31;
        float s = 0.f;
#pragma unroll
        for (int d = 0; d < 64; d++) s += Qs[qi][d] * Ks[kj][d];
        s *= 0.125f;
        P[qi][kj] = (ms[qi] && ms[kj]) ? s : -3.402823466e38f;
    }
    __syncthreads();

    if (tid < 32) {
        float mx = -3.402823466e38f;
#pragma unroll
        for (int j = 0; j < 32; j++) mx = fmaxf(mx, P[tid][j]);
        float sum = 0.f;
#pragma unroll
        for (int j = 0; j < 32; j++) { float e = expf(P[tid][j] - mx); P[tid][j] = e; sum += e; }
        const float inv = 1.f / sum;
#pragma unroll
        for (int j = 0; j < 32; j++) P[tid][j] = (ms[tid] && ms[j]) ? P[tid][j] * inv : 0.f;
    }
    __syncthreads();

    for (int i = tid; i < NSPAN * DHEAD; i += 128) {
        const int qi = i >> 6, d = i & 63;
        float s = 0.f;
#pragma unroll
        for (int j = 0; j < 32; j++) s += P[qi][j] * Vs[j][d];
        g_ctx[(rowbase + qi) * HH + col0 + d] = s;
    }
}

// ============ classifier: warp per row, N=5 ============
__global__ void __launch_bounds__(256)
clf_kernel(const float* __restrict__ W, const float* __restrict__ b, float* __restrict__ out)
{
    __shared__ float ws[NCLS * HH];
    const int tid = threadIdx.x;
    for (int i = tid; i < NCLS * HH; i += 256) ws[i] = W[i];
    __syncthreads();

    const int warp = tid >> 5, lane = tid & 31;
    const int row = blockIdx.x * 8 + warp;
    const float* a = g_attn + (size_t)row * HH;

    float acc[NCLS] = {0.f, 0.f, 0.f, 0.f, 0.f};
    for (int k = lane; k < HH; k += 32) {
        const float av = a[k];
#pragma unroll
        for (int c = 0; c < NCLS; c++) acc[c] += av * ws[c * HH + k];
    }
#pragma unroll
    for (int c = 0; c < NCLS; c++) {
#pragma unroll
        for (int o = 16; o > 0; o >>= 1) acc[c] += __shfl_down_sync(0xffffffffu, acc[c], o);
    }
    if (lane == 0) {
#pragma unroll
        for (int c = 0; c < NCLS; c++) out[(size_t)row * NCLS + c] = acc[c] + b[c];
    }
}

// ============ launch ============
extern "C" void kernel_launch(void* const* d_in, const int* in_sizes, int n_in,
                              void* d_out, int out_size)
{
    const float* enc_in  = (const float*)d_in[0];
    const float* W_ih    = (const float*)d_in[1];
    const float* W_hh    = (const float*)d_in[2];
    const float* b_ih    = (const float*)d_in[3];
    const float* b_hh    = (const float*)d_in[4];
    const float* ln_g    = (const float*)d_in[5];
    const float* ln_b    = (const float*)d_in[6];
    const float* Wq      = (const float*)d_in[7];
    const float* bq      = (const float*)d_in[8];
    const float* Wk      = (const float*)d_in[9];
    const float* bk      = (const float*)d_in[10];
    const float* Wv      = (const float*)d_in[11];
    const float* bv      = (const float*)d_in[12];
    const float* Wo      = (const float*)d_in[13];
    const float* bo      = (const float*)d_in[14];
    const float* aln_g   = (const float*)d_in[15];
    const float* aln_b   = (const float*)d_in[16];
    const float* clf_W   = (const float*)d_in[17];
    const float* clf_b   = (const float*)d_in[18];
    const int*   heads   = (const int*)d_in[19];
    const int*   tails   = (const int*)d_in[20];
    const int*   mask    = (const int*)d_in[21];
    float* out = (float*)d_out;

    float *gates, *pool, *q, *k, *v, *ctx, *wo_buf;
    cudaGetSymbolAddress((void**)&gates,  g_gates);
    cudaGetSymbolAddress((void**)&pool,   g_pool);
    cudaGetSymbolAddress((void**)&q,      g_q);
    cudaGetSymbolAddress((void**)&k,      g_k);
    cudaGetSymbolAddress((void**)&v,      g_v);
    cudaGetSymbolAddress((void**)&ctx,    g_ctx);
    cudaGetSymbolAddress((void**)&wo_buf, g_wo);

    // 0. reset barrier counters
    reset_kernel<<<1, 32>>>();

    // 1. gates = X @ W_ih^T + b_ih + b_hh   (tf32, pipelined)
    mma_gemm_nt<<<dim3(HX4 / 128, (BB * SS) / 128), 256>>>(
        enc_in, W_ih, b_ih, b_hh, gates, HX4, HH);

    // 2. persistent LSTM (warp-k-split, balanced 2-phase MMA)
    const int smem = (32 * WSTRIDE * 2 + 16 * WSTRIDE * 2) * (int)sizeof(__nv_bfloat16)
                   + (8 * 16 * 36 + 128) * (int)sizeof(float);
    cudaFuncSetAttribute(lstm_kernel, cudaFuncAttributeMaxDynamicSharedMemorySize, smem);
    lstm_kernel<<<NCTA, 256, smem>>>(W_hh);

    // 3. span pool + LN
    pool_ln_kernel<<<BB * NSPAN, 256>>>(ln_g, ln_b, heads, tails);

    // 4. fused QKV projections (tf32)
    mma_gemm_qkv<<<dim3(HH / 128, (BB * NSPAN) / 128, 3), 256>>>(
        pool, Wq, Wk, Wv, bq, bk, bv, q, k, v);

    // 5. attention
    attn_kernel<<<BB * NHEADS, 128>>>(mask);

    // 6. output projection (tf32)
    mma_gemm_nt<<<dim3(HH / 128, (BB * NSPAN) / 128), 256>>>(ctx, Wo, bo, nullptr, wo_buf, HH, HH);

    // 7. residual LN
    ln_res_kernel<<<BB * NSPAN, 256>>>(aln_g, aln_b);

    // 8. classifier -> d_out [B,NS,L]
    clf_kernel<<<(BB * NSPAN) / 8, 256>>>(clf_W, clf_b, out);
}

// round 16
// speedup vs baseline: 1.7510x; 1.0165x over previous
#include <cuda_runtime.h>
#include <cuda_bf16.h>
#include <math.h>
#include <stdint.h>

#define BB      16
#define SS      1024
#define HH      1024
#define HX4     4096
#define NSPAN   32
#define NHEADS  16
#define DHEAD   64
#define NCLS    5
#define NCTA    128
#define UPC     8
#define WSTRIDE 1032   // padded bf16 row stride -> conflict-free ldmatrix
#define GK      36     // gates GEMM smem row stride (floats), conflict-free

// ---------------- device scratch ----------------
__device__ float g_gates[(size_t)BB * SS * HX4];   // [b][s][4H]
__device__ float g_enc  [(size_t)BB * SS * HH];
__device__ float g_xr   [(size_t)BB * SS * HH];    // tf32-rounded X
__device__ float g_wr   [(size_t)HX4 * HH];        // tf32-rounded W_ih
__device__ __nv_bfloat16 g_hhi[2][BB * HH];
__device__ __nv_bfloat16 g_hlo[2][BB * HH];
__device__ int g_cnt[4 * 32];                      // 4 group counters, 128B apart
__device__ float g_pool [BB * NSPAN * HH];
__device__ float g_q    [BB * NSPAN * HH];
__device__ float g_k    [BB * NSPAN * HH];
__device__ float g_v    [BB * NSPAN * HH];
__device__ float g_ctx  [BB * NSPAN * HH];
__device__ float g_wo   [BB * NSPAN * HH];
__device__ float g_attn [BB * NSPAN * HH];

// ---------------- asm helpers ----------------
__device__ __forceinline__ uint32_t f2tf32(float x) {
    uint32_t r; asm("cvt.rna.tf32.f32 %0, %1;" : "=r"(r) : "f"(x)); return r;
}
__device__ __forceinline__ void mma_tf32(float* c, const uint32_t* a, const uint32_t* b) {
    asm volatile("mma.sync.aligned.m16n8k8.row.col.f32.tf32.tf32.f32 "
        "{%0,%1,%2,%3}, {%4,%5,%6,%7}, {%8,%9}, {%0,%1,%2,%3};"
        : "+f"(c[0]), "+f"(c[1]), "+f"(c[2]), "+f"(c[3])
        : "r"(a[0]), "r"(a[1]), "r"(a[2]), "r"(a[3]), "r"(b[0]), "r"(b[1]));
}
__device__ __forceinline__ void mma_bf16(float* c, const uint32_t* a, const uint32_t* b) {
    asm volatile("mma.sync.aligned.m16n8k16.row.col.f32.bf16.bf16.f32 "
        "{%0,%1,%2,%3}, {%4,%5,%6,%7}, {%8,%9}, {%0,%1,%2,%3};"
        : "+f"(c[0]), "+f"(c[1]), "+f"(c[2]), "+f"(c[3])
        : "r"(a[0]), "r"(a[1]), "r"(a[2]), "r"(a[3]), "r"(b[0]), "r"(b[1]));
}
__device__ __forceinline__ void ldsm_x4(uint32_t* r, uint32_t addr) {
    asm volatile("ldmatrix.sync.aligned.m8n8.x4.shared.b16 {%0,%1,%2,%3}, [%4];"
        : "=r"(r[0]), "=r"(r[1]), "=r"(r[2]), "=r"(r[3]) : "r"(addr));
}
__device__ __forceinline__ uint32_t smem_u32(const void* p) {
    uint32_t a;
    asm("{ .reg .u64 t; cvta.to.shared.u64 t, %1; cvt.u32.u64 %0, t; }" : "=r"(a) : "l"(p));
    return a;
}
__device__ __forceinline__ void bsplit(float w, __nv_bfloat16& hi, __nv_bfloat16& lo) {
    hi = __float2bfloat16(w);
    lo = __float2bfloat16(w - __bfloat162float(hi));
}
__device__ __forceinline__ int ld_acq(const int* p) {
    int v; asm volatile("ld.acquire.gpu.global.b32 %0, [%1];" : "=r"(v) : "l"(p)); return v;
}
__device__ __forceinline__ void red_add_release(int* p, int v) {
    asm volatile("red.release.gpu.global.add.s32 [%0], %1;" :: "l"(p), "r"(v) : "memory");
}
__device__ __forceinline__ void cp16(uint32_t s, const void* g) {
    asm volatile("cp.async.cg.shared.global [%0], [%1], 16;" :: "r"(s), "l"(g));
}
#define CP_COMMIT() asm volatile("cp.async.commit_group;" ::: "memory")
#define CP_WAIT(n)  asm volatile("cp.async.wait_group %0;" :: "n"(n) : "memory")

__global__ void reset_kernel()
{
    if (threadIdx.x < 4) g_cnt[threadIdx.x * 32] = 0;
}

// ============ tf32 pre-round pass (grid-stride float4) ============
__global__ void __launch_bounds__(256)
round_kernel(const float* __restrict__ src, float* __restrict__ dst, int n4)
{
    for (int i = blockIdx.x * 256 + threadIdx.x; i < n4; i += gridDim.x * 256) {
        float4 v = ((const float4*)src)[i];
        v.x = __uint_as_float(f2tf32(v.x));
        v.y = __uint_as_float(f2tf32(v.y));
        v.z = __uint_as_float(f2tf32(v.z));
        v.w = __uint_as_float(f2tf32(v.w));
        ((float4*)dst)[i] = v;
    }
}

// =====================================================================
// Gates GEMM: C[16384,4096] = Xr @ Wr^T + b1 + b2 (tf32, pre-rounded).
// Double-buffered cp.async (32-k slabs), [m][GK] smem, 2 CTAs/SM.
// =====================================================================
__global__ void __launch_bounds__(256, 2)
tf32_gemm_gates(const float* __restrict__ b1, const float* __restrict__ b2,
                float* __restrict__ C)
{
    extern __shared__ float smf[];
    float* Asm = smf;                        // [2][128][GK]
    float* Wsm = smf + 2 * 128 * GK;         // [2][128][GK]
    const uint32_t sA = smem_u32(Asm), sW = smem_u32(Wsm);
    const uint32_t BUFB = 128 * GK * 4;

    const int tid = threadIdx.x;
    const int lane = tid & 31, warp = tid >> 5;
    const int wm = (warp >> 2) * 64;
    const int wnn = (warp & 3) * 32;
    const int tig = lane & 3, grp = lane >> 2;

    const int n0 = blockIdx.x * 128, m0 = blockIdx.y * 128;

    // loader mapping: row lr, 16 cols starting at (tid&1)*16
    const int lr = tid >> 1, kb = (tid & 1) * 16;
    const float* Ap = g_xr + (size_t)(m0 + lr) * HH + kb;
    const float* Wp = g_wr + (size_t)(n0 + lr) * HH + kb;
    const uint32_t dstoff = ((uint32_t)lr * GK + kb) * 4;

    float c[4][4][4];
#pragma unroll
    for (int mi = 0; mi < 4; mi++)
#pragma unroll
        for (int ni = 0; ni < 4; ni++)
#pragma unroll
            for (int j = 0; j < 4; j++) c[mi][ni][j] = 0.f;

    // prefetch slab 0 into buf 0
#pragma unroll
    for (int j = 0; j < 4; j++) {
        cp16(sA + dstoff + j * 16, Ap + j * 4);
        cp16(sW + dstoff + j * 16, Wp + j * 4);
    }
    CP_COMMIT();

    for (int s = 0; s < 32; s++) {
        if (s + 1 < 32) {
            const int k = (s + 1) * 32;
            const uint32_t d = (uint32_t)((s + 1) & 1) * BUFB + dstoff;
#pragma unroll
            for (int j = 0; j < 4; j++) {
                cp16(sA + d + j * 16, Ap + k + j * 4);
                cp16(sW + d + j * 16, Wp + k + j * 4);
            }
            CP_COMMIT();
            CP_WAIT(1);
        } else {
            CP_WAIT(0);
        }
        __syncthreads();

        const float* Ab = Asm + (s & 1) * (128 * GK);
        const float* Wb = Wsm + (s & 1) * (128 * GK);
#pragma unroll
        for (int ks = 0; ks < 32; ks += 8) {
            uint32_t a[4][4], b[4][2];
#pragma unroll
            for (int mi = 0; mi < 4; mi++) {
                const int rb = wm + mi * 16 + grp;
                a[mi][0] = __float_as_uint(Ab[rb * GK + ks + tig]);
                a[mi][1] = __float_as_uint(Ab[(rb + 8) * GK + ks + tig]);
                a[mi][2] = __float_as_uint(Ab[rb * GK + ks + tig + 4]);
                a[mi][3] = __float_as_uint(Ab[(rb + 8) * GK + ks + tig + 4]);
            }
#pragma unroll
            for (int ni = 0; ni < 4; ni++) {
                const int nb = wnn + ni * 8 + grp;
                b[ni][0] = __float_as_uint(Wb[nb * GK + ks + tig]);
                b[ni][1] = __float_as_uint(Wb[nb * GK + ks + tig + 4]);
            }
#pragma unroll
            for (int mi = 0; mi < 4; mi++)
#pragma unroll
                for (int ni = 0; ni < 4; ni++)
                    mma_tf32(c[mi][ni], a[mi], b[ni]);
        }
        __syncthreads();
    }

#pragma unroll
    for (int ni = 0; ni < 4; ni++) {
        const int col = n0 + wnn + ni * 8 + tig * 2;
        const float bias0 = b1[col] + b2[col];
        const float bias1 = b1[col + 1] + b2[col + 1];
#pragma unroll
        for (int mi = 0; mi < 4; mi++) {
            const int row = m0 + wm + mi * 16 + grp;
            C[(size_t)row * HX4 + col]           = c[mi][ni][0] + bias0;
            C[(size_t)row * HX4 + col + 1]       = c[mi][ni][1] + bias1;
            C[(size_t)(row + 8) * HX4 + col]     = c[mi][ni][2] + bias0;
            C[(size_t)(row + 8) * HX4 + col + 1] = c[mi][ni][3] + bias1;
        }
    }
}

// =====================================================================
// tf32 GEMM (QKV / Wo) -- unchanged
// =====================================================================
__device__ __forceinline__ void gemm_body(
    const float* __restrict__ A, const float* __restrict__ W,
    const float* __restrict__ b1, const float* __restrict__ b2,
    float* __restrict__ C, int N, int K,
    uint32_t (*As)[136], uint32_t (*Ws)[136])
{
    const int tid = threadIdx.x;
    const int lane = tid & 31, warp = tid >> 5;
    const int wm = (warp >> 2) * 64;
    const int wnn = (warp & 3) * 32;
    const int tig = lane & 3, grp = lane >> 2;

    const int n0 = blockIdx.x * 128, m0 = blockIdx.y * 128;
    const int lr = tid >> 1;
    const int kq = (tid & 1) * 8;

    float c[4][4][4];
#pragma unroll
    for (int mi = 0; mi < 4; mi++)
#pragma unroll
        for (int ni = 0; ni < 4; ni++)
#pragma unroll
            for (int j = 0; j < 4; j++) c[mi][ni][j] = 0.f;

    const float* Ap = A + (size_t)(m0 + lr) * K + kq;
    const float* Wp = W + (size_t)(n0 + lr) * K + kq;

    float4 av0 = *(const float4*)(Ap);
    float4 av1 = *(const float4*)(Ap + 4);
    float4 wv0 = *(const float4*)(Wp);
    float4 wv1 = *(const float4*)(Wp + 4);

    for (int k0 = 0; k0 < K; k0 += 16) {
        As[kq+0][lr] = f2tf32(av0.x); As[kq+1][lr] = f2tf32(av0.y);
        As[kq+2][lr] = f2tf32(av0.z); As[kq+3][lr] = f2tf32(av0.w);
        As[kq+4][lr] = f2tf32(av1.x); As[kq+5][lr] = f2tf32(av1.y);
        As[kq+6][lr] = f2tf32(av1.z); As[kq+7][lr] = f2tf32(av1.w);
        Ws[kq+0][lr] = f2tf32(wv0.x); Ws[kq+1][lr] = f2tf32(wv0.y);
        Ws[kq+2][lr] = f2tf32(wv0.z); Ws[kq+3][lr] = f2tf32(wv0.w);
        Ws[kq+4][lr] = f2tf32(wv1.x); Ws[kq+5][lr] = f2tf32(wv1.y);
        Ws[kq+6][lr] = f2tf32(wv1.z); Ws[kq+7][lr] = f2tf32(wv1.w);
        __syncthreads();

        if (k0 + 16 < K) {
            av0 = *(const float4*)(Ap + k0 + 16);
            av1 = *(const float4*)(Ap + k0 + 20);
            wv0 = *(const float4*)(Wp + k0 + 16);
            wv1 = *(const float4*)(Wp + k0 + 20);
        }

#pragma unroll
        for (int ks = 0; ks < 16; ks += 8) {
            uint32_t a[4][4], b[4][2];
#pragma unroll
            for (int mi = 0; mi < 4; mi++) {
                const int rb = wm + mi * 16 + grp;
                a[mi][0] = As[ks + tig][rb];
                a[mi][1] = As[ks + tig][rb + 8];
                a[mi][2] = As[ks + tig + 4][rb];
                a[mi][3] = As[ks + tig + 4][rb + 8];
            }
#pragma unroll
            for (int ni = 0; ni < 4; ni++) {
                const int nb = wnn + ni * 8 + grp;
                b[ni][0] = Ws[ks + tig][nb];
                b[ni][1] = Ws[ks + tig + 4][nb];
            }
#pragma unroll
            for (int mi = 0; mi < 4; mi++)
#pragma unroll
                for (int ni = 0; ni < 4; ni++)
                    mma_tf32(c[mi][ni], a[mi], b[ni]);
        }
        __syncthreads();
    }

#pragma unroll
    for (int ni = 0; ni < 4; ni++) {
        const int col = n0 + wnn + ni * 8 + tig * 2;
        float bias0 = b1[col], bias1 = b1[col + 1];
        if (b2) { bias0 += b2[col]; bias1 += b2[col + 1]; }
#pragma unroll
        for (int mi = 0; mi < 4; mi++) {
            const int row = m0 + wm + mi * 16 + grp;
            C[(size_t)row * N + col]           = c[mi][ni][0] + bias0;
            C[(size_t)row * N + col + 1]       = c[mi][ni][1] + bias1;
            C[(size_t)(row + 8) * N + col]     = c[mi][ni][2] + bias0;
            C[(size_t)(row + 8) * N + col + 1] = c[mi][ni][3] + bias1;
        }
    }
}

__global__ void __launch_bounds__(256)
mma_gemm_nt(const float* __restrict__ A, const float* __restrict__ W,
            const float* __restrict__ b1, const float* __restrict__ b2,
            float* __restrict__ C, int N, int K)
{
    __shared__ uint32_t As[16][136];
    __shared__ uint32_t Ws[16][136];
    gemm_body(A, W, b1, b2, C, N, K, As, Ws);
}

__global__ void __launch_bounds__(256)
mma_gemm_qkv(const float* __restrict__ A,
             const float* __restrict__ Wq, const float* __restrict__ Wk, const float* __restrict__ Wv,
             const float* __restrict__ bq, const float* __restrict__ bk, const float* __restrict__ bv,
             float* __restrict__ Oq, float* __restrict__ Ok, float* __restrict__ Ov)
{
    __shared__ uint32_t As[16][136];
    __shared__ uint32_t Ws[16][136];
    const int z = blockIdx.z;
    const float* W = (z == 0) ? Wq : (z == 1) ? Wk : Wv;
    const float* b = (z == 0) ? bq : (z == 1) ? bk : bv;
    float* O       = (z == 0) ? Oq : (z == 1) ? Ok : Ov;
    gemm_body(A, W, b, nullptr, O, HH, HH, As, Ws);
}

// =====================================================================
// Persistent LSTM (R15, best): warp-k-split, balanced 2-phase MMA.
// =====================================================================
__global__ void __launch_bounds__(256, 1)
lstm_kernel(const float* __restrict__ Whh)
{
    extern __shared__ char smraw[];
    __nv_bfloat16* Whi = (__nv_bfloat16*)smraw;
    __nv_bfloat16* Wlo = Whi + 32 * WSTRIDE;
    __nv_bfloat16* hhi = Wlo + 32 * WSTRIDE;
    __nv_bfloat16* hlo = hhi + 16 * WSTRIDE;
    float* gbuf = (float*)(hlo + 16 * WSTRIDE);          // [8][16][36]
    float* cst  = gbuf + 8 * 16 * 36;                    // [128]

    const int tid = threadIdx.x;
    const int cta = blockIdx.x;
    const int lane = tid & 31, warp = tid >> 5;
    const int grp = lane >> 2, tig = lane & 3;

    for (int i = tid; i < 32 * 1024; i += 256) {
        const int r = i >> 10, k = i & 1023;
        const int jrow = (r >> 3) * 1024 + cta * UPC + (r & 7);
        __nv_bfloat16 hi, lo;
        bsplit(Whh[(size_t)jrow * HH + k], hi, lo);
        Whi[r * WSTRIDE + k] = hi;
        Wlo[r * WSTRIDE + k] = lo;
    }
    if (tid < 128) cst[tid] = 0.f;
    __syncthreads();

    const uint32_t s_hhi = smem_u32(hhi), s_hlo = smem_u32(hlo);
    const uint32_t s_whi = smem_u32(Whi), s_wlo = smem_u32(Wlo);
    const uint32_t koffA = (uint32_t)warp * 128;
    const uint32_t koffB2 = koffA + 1024;

    const uint32_t aBase = (lane & 15) * (WSTRIDE * 2) + (lane >> 4) * 16;
    const uint32_t ahiA = s_hhi + aBase + koffA;
    const uint32_t aloA = s_hlo + aBase + koffA;
    const uint32_t ahiB = s_hhi + aBase + koffB2;
    const uint32_t aloB = s_hlo + aBase + koffB2;
    const uint32_t brow = (uint32_t)(lane & 7) + ((lane >> 4) << 3);
    const uint32_t bcol = ((lane >> 3) & 1) * 16;
    const uint32_t bB = brow * (WSTRIDE * 2) + bcol;
    const uint32_t bhiA1 = s_whi + bB + koffA,  bhiA2 = bhiA1 + 16 * (WSTRIDE * 2);
    const uint32_t bloA1 = s_wlo + bB + koffA,  bloA2 = bloA1 + 16 * (WSTRIDE * 2);
    const uint32_t bhiB1 = s_whi + bB + koffB2, bhiB2 = bhiB1 + 16 * (WSTRIDE * 2);
    const uint32_t bloB1 = s_wlo + bB + koffB2, bloB2 = bloB1 + 16 * (WSTRIDE * 2);

    const int su = tid & 7, sb = tid >> 3;
    const int unit = cta * UPC + su;
    int* mycnt = &g_cnt[(cta & 3) * 32];
    float* pw = gbuf + warp * (16 * 36);

    for (int t = 0; t < SS; t++) {
        float gt[4] = {0.f, 0.f, 0.f, 0.f};
        if (tid < 128) {
            const size_t goff = ((size_t)sb * SS + t) * HX4 + cta * UPC + su;
#pragma unroll
            for (int g = 0; g < 4; g++) gt[g] = g_gates[goff + g * 1024];
        }

        float c[4][4];
#pragma unroll
        for (int n = 0; n < 4; n++)
#pragma unroll
            for (int j = 0; j < 4; j++) c[n][j] = 0.f;

        if (t > 0) {
            if (warp == 0 && lane < 4) {
                const int tgt = 32 * t;
                while (ld_acq(&g_cnt[lane * 32]) < tgt) { }
            }
            __syncthreads();

            const __nv_bfloat16* shi = g_hhi[t & 1];
            const __nv_bfloat16* slo = g_hlo[t & 1];
#pragma unroll
            for (int ph = 0; ph < 2; ph++) {
#pragma unroll
                for (int j = 0; j < 4; j++) {
                    const int i = tid + j * 256;
                    const int row = i >> 6;
                    const int col = ph * 512 + (i & 63) * 8;
                    cp16(s_hhi + row * (WSTRIDE * 2) + col * 2, shi + row * 1024 + col);
                    cp16(s_hlo + row * (WSTRIDE * 2) + col * 2, slo + row * 1024 + col);
                }
                CP_COMMIT();
            }

            CP_WAIT(1); __syncthreads();
#pragma unroll
            for (int kt = 0; kt < 4; kt++) {
                const uint32_t off = kt * 32;
                uint32_t ah[4], al[4], bh1[4], bh2[4], bl1[4], bl2[4];
                ldsm_x4(ah, ahiA + off);
                ldsm_x4(al, aloA + off);
                ldsm_x4(bh1, bhiA1 + off);
                ldsm_x4(bh2, bhiA2 + off);
                ldsm_x4(bl1, bloA1 + off);
                ldsm_x4(bl2, bloA2 + off);
                mma_bf16(c[0], ah, bh1);  mma_bf16(c[1], ah, bh1 + 2);
                mma_bf16(c[2], ah, bh2);  mma_bf16(c[3], ah, bh2 + 2);
                mma_bf16(c[0], al, bh1);  mma_bf16(c[1], al, bh1 + 2);
                mma_bf16(c[2], al, bh2);  mma_bf16(c[3], al, bh2 + 2);
                mma_bf16(c[0], ah, bl1);  mma_bf16(c[1], ah, bl1 + 2);
                mma_bf16(c[2], ah, bl2);  mma_bf16(c[3], ah, bl2 + 2);
            }
            CP_WAIT(0); __syncthreads();
#pragma unroll
            for (int kt = 0; kt < 4; kt++) {
                const uint32_t off = kt * 32;
                uint32_t ah[4], al[4], bh1[4], bh2[4], bl1[4], bl2[4];
                ldsm_x4(ah, ahiB + off);
                ldsm_x4(al, aloB + off);
                ldsm_x4(bh1, bhiB1 + off);
                ldsm_x4(bh2, bhiB2 + off);
                ldsm_x4(bl1, bloB1 + off);
                ldsm_x4(bl2, bloB2 + off);
                mma_bf16(c[0], ah, bh1);  mma_bf16(c[1], ah, bh1 + 2);
                mma_bf16(c[2], ah, bh2);  mma_bf16(c[3], ah, bh2 + 2);
                mma_bf16(c[0], al, bh1);  mma_bf16(c[1], al, bh1 + 2);
                mma_bf16(c[2], al, bh2);  mma_bf16(c[3], al, bh2 + 2);
                mma_bf16(c[0], ah, bl1);  mma_bf16(c[1], ah, bl1 + 2);
                mma_bf16(c[2], ah, bl2);  mma_bf16(c[3], ah, bl2 + 2);
            }
        }

#pragma unroll
        for (int n = 0; n < 4; n++) {
            const int row = n * 8 + tig * 2;
            *(float2*)(pw + grp * 36 + row)       = make_float2(c[n][0], c[n][1]);
            *(float2*)(pw + (grp + 8) * 36 + row) = make_float2(c[n][2], c[n][3]);
        }
        __syncthreads();

        float h = 0.f;
        if (tid < 128) {
            float iv = gt[0], fv = gt[1], gv = gt[2], ov = gt[3];
#pragma unroll
            for (int w = 0; w < 8; w++) {
                const float* p = gbuf + w * (16 * 36) + sb * 36 + su;
                iv += p[0];
                fv += p[8];
                gv += p[16];
                ov += p[24];
            }
            const float ig = 1.f / (1.f + expf(-iv));
            const float fg = 1.f / (1.f + expf(-fv));
            const float og = 1.f / (1.f + expf(-ov));
            const float cv = fg * cst[tid] + ig * tanhf(gv);
            cst[tid] = cv;
            h = og * tanhf(cv);
            __nv_bfloat16 hi, lo;
            bsplit(h, hi, lo);
            g_hhi[(t + 1) & 1][sb * HH + unit] = hi;
            g_hlo[(t + 1) & 1][sb * HH + unit] = lo;
        }
        __syncthreads();
        if (tid == 0) red_add_release(mycnt, 1);
        if (tid < 128)
            g_enc[((size_t)sb * SS + t) * HH + unit] = h;
    }
}

// ============ block reduction helper (256 threads) ============
__device__ __forceinline__ float blk_sum256(float v, float* red)
{
#pragma unroll
    for (int o = 16; o > 0; o >>= 1) v += __shfl_down_sync(0xffffffffu, v, o);
    const int tid = threadIdx.x;
    if ((tid & 31) == 0) red[tid >> 5] = v;
    __syncthreads();
    if (tid < 32) {
        float x = (tid < 8) ? red[tid] : 0.f;
#pragma unroll
        for (int o = 4; o > 0; o >>= 1) x += __shfl_down_sync(0xffffffffu, x, o);
        if (tid == 0) red[0] = x;
    }
    __syncthreads();
    const float s = red[0];
    __syncthreads();
    return s;
}

// ============ span mean-pool + LayerNorm ============
__global__ void pool_ln_kernel(const float* __restrict__ gamma, const float* __restrict__ beta,
                               const int* __restrict__ heads, const int* __restrict__ tails)
{
    __shared__ float red[32];
    const int span = blockIdx.x;
    const int tid = threadIdx.x;
    const int b = span >> 5;
    const int head = heads[span], tail = tails[span];

    float4 acc = make_float4(0.f, 0.f, 0.f, 0.f);
    for (int s = head + 1; s < tail; s++) {
        const float4 v = *(const float4*)(g_enc + ((size_t)b * SS + s) * HH + tid * 4);
        acc.x += v.x; acc.y += v.y; acc.z += v.z; acc.w += v.w;
    }
    const float invc = 1.f / (float)(tail - head - 1);
    acc.x *= invc; acc.y *= invc; acc.z *= invc; acc.w *= invc;

    const float mu = blk_sum256(acc.x + acc.y + acc.z + acc.w, red) * (1.f / HH);
    const float dx = acc.x - mu, dy = acc.y - mu, dz = acc.z - mu, dw = acc.w - mu;
    const float var = blk_sum256(dx*dx + dy*dy + dz*dz + dw*dw, red) * (1.f / HH);
    const float rstd = rsqrtf(var + 1e-7f);

    const int h = tid * 4;
    const float4 gm = *(const float4*)(gamma + h);
    const float4 bt = *(const float4*)(beta + h);
    float4 o = make_float4(dx*rstd*gm.x + bt.x, dy*rstd*gm.y + bt.y,
                           dz*rstd*gm.z + bt.z, dw*rstd*gm.w + bt.w);
    *(float4*)(g_pool + (size_t)span * HH + h) = o;
}

// ============ residual LayerNorm ============
__global__ void ln_res_kernel(const float* __restrict__ gamma, const float* __restrict__ beta)
{
    __shared__ float red[32];
    const int row = blockIdx.x;
    const int tid = threadIdx.x;
    const size_t off = (size_t)row * HH + tid * 4;

    float4 x = *(const float4*)(g_wo + off);
    const float4 p = *(const float4*)(g_pool + off);
    x.x += p.x; x.y += p.y; x.z += p.z; x.w += p.w;

    const float mu = blk_sum256(x.x + x.y + x.z + x.w, red) * (1.f / HH);
    const float dx = x.x - mu, dy = x.y - mu, dz = x.z - mu, dw = x.w - mu;
    const float var = blk_sum256(dx*dx + dy*dy + dz*dz + dw*dw, red) * (1.f / HH);
    const float rstd = rsqrtf(var + 1e-7f);

    const int h = tid * 4;
    const float4 gm = *(const float4*)(gamma + h);
    const float4 bt = *(const float4*)(beta + h);
    float4 o = make_float4(dx*rstd*gm.x + bt.x, dy*rstd*gm.y + bt.y,
                           dz*rstd*gm.z + bt.z, dw*rstd*gm.w + bt.w);
    *(float4*)(g_attn + off) = o;
}

// ============ span attention: one CTA per (b, head) ============
__global__ void attn_kernel(const int* __restrict__ mask)
{
    __shared__ float Qs[32][65], Ks[32][65], Vs[32][65];
    __shared__ float P[32][33];
    __shared__ int ms[32];

    const int bh = blockIdx.x;
    const int b = bh / NHEADS, hd = bh % NHEADS;
    const int tid = threadIdx.x;
    const size_t rowbase = (size_t)b * NSPAN;
    const int col0 = hd * DHEAD;

    for (int i = tid; i < NSPAN * DHEAD; i += 128) {
        const int n = i >> 6, d = i & 63;
        const size_t off = (rowbase + n) * HH + col0 + d;
        Qs[n][d] = g_q[off];
        Ks[n][d] = g_k[off];
        Vs[n][d] = g_v[off];
    }
    if (tid < 32) ms[tid] = mask[b * NSPAN + tid];
    __syncthreads();

    for (int i = tid; i < 1024; i += 128) {
        const int qi = i >> 5, kj = i & 31;
        float s = 0.f;
#pragma unroll
        for (int d = 0; d < 64; d++) s += Qs[qi][d] * Ks[kj][d];
        s *= 0.125f;
        P[qi][kj] = (ms[qi] && ms[kj]) ? s : -3.402823466e38f;
    }
    __syncthreads();

    if (tid < 32) {
        float mx = -3.402823466e38f;
#pragma unroll
        for (int j = 0; j < 32; j++) mx = fmaxf(mx, P[tid][j]);
        float sum = 0.f;
#pragma unroll
        for (int j = 0; j < 32; j++) { float e = expf(P[tid][j] - mx); P[tid][j] = e; sum += e; }
        const float inv = 1.f / sum;
#pragma unroll
        for (int j = 0; j < 32; j++) P[tid][j] = (ms[tid] && ms[j]) ? P[tid][j] * inv : 0.f;
    }
    __syncthreads();

    for (int i = tid; i < NSPAN * DHEAD; i += 128) {
        const int qi = i >> 6, d = i & 63;
        float s = 0.f;
#pragma unroll
        for (int j = 0; j < 32; j++) s += P[qi][j] * Vs[j][d];
        g_ctx[(rowbase + qi) * HH + col0 + d] = s;
    }
}

// ============ classifier: warp per row, N=5 ============
__global__ void __launch_bounds__(256)
clf_kernel(const float* __restrict__ W, const float* __restrict__ b, float* __restrict__ out)
{
    __shared__ float ws[NCLS * HH];
    const int tid = threadIdx.x;
    for (int i = tid; i < NCLS * HH; i += 256) ws[i] = W[i];
    __syncthreads();

    const int warp = tid >> 5, lane = tid & 31;
    const int row = blockIdx.x * 8 + warp;
    const float* a = g_attn + (size_t)row * HH;

    float acc[NCLS] = {0.f, 0.f, 0.f, 0.f, 0.f};
    for (int k = lane; k < HH; k += 32) {
        const float av = a[k];
#pragma unroll
        for (int c = 0; c < NCLS; c++) acc[c] += av * ws[c * HH + k];
    }
#pragma unroll
    for (int c = 0; c < NCLS; c++) {
#pragma unroll
        for (int o = 16; o > 0; o >>= 1) acc[c] += __shfl_down_sync(0xffffffffu, acc[c], o);
    }
    if (lane == 0) {
#pragma unroll
        for (int c = 0; c < NCLS; c++) out[(size_t)row * NCLS + c] = acc[c] + b[c];
    }
}

// ============ launch ============
extern "C" void kernel_launch(void* const* d_in, const int* in_sizes, int n_in,
                              void* d_out, int out_size)
{
    const float* enc_in  = (const float*)d_in[0];
    const float* W_ih    = (const float*)d_in[1];
    const float* W_hh    = (const float*)d_in[2];
    const float* b_ih    = (const float*)d_in[3];
    const float* b_hh    = (const float*)d_in[4];
    const float* ln_g    = (const float*)d_in[5];
    const float* ln_b    = (const float*)d_in[6];
    const float* Wq      = (const float*)d_in[7];
    const float* bq      = (const float*)d_in[8];
    const float* Wk      = (const float*)d_in[9];
    const float* bk      = (const float*)d_in[10];
    const float* Wv      = (const float*)d_in[11];
    const float* bv      = (const float*)d_in[12];
    const float* Wo      = (const float*)d_in[13];
    const float* bo      = (const float*)d_in[14];
    const float* aln_g   = (const float*)d_in[15];
    const float* aln_b   = (const float*)d_in[16];
    const float* clf_W   = (const float*)d_in[17];
    const float* clf_b   = (const float*)d_in[18];
    const int*   heads   = (const int*)d_in[19];
    const int*   tails   = (const int*)d_in[20];
    const int*   mask    = (const int*)d_in[21];
    float* out = (float*)d_out;

    float *gates, *pool, *q, *k, *v, *ctx, *wo_buf, *xr, *wr;
    cudaGetSymbolAddress((void**)&gates,  g_gates);
    cudaGetSymbolAddress((void**)&pool,   g_pool);
    cudaGetSymbolAddress((void**)&q,      g_q);
    cudaGetSymbolAddress((void**)&k,      g_k);
    cudaGetSymbolAddress((void**)&v,      g_v);
    cudaGetSymbolAddress((void**)&ctx,    g_ctx);
    cudaGetSymbolAddress((void**)&wo_buf, g_wo);
    cudaGetSymbolAddress((void**)&xr,     g_xr);
    cudaGetSymbolAddress((void**)&wr,     g_wr);

    // 0. reset barrier counters
    reset_kernel<<<1, 32>>>();

    // 1a. pre-round X and W_ih to tf32
    round_kernel<<<2048, 256>>>(enc_in, xr, (BB * SS * HH) / 4);
    round_kernel<<<1024, 256>>>(W_ih, wr, (HX4 * HH) / 4);

    // 1b. gates = Xr @ Wr^T + b_ih + b_hh (double-buffered cp.async, 2 CTAs/SM)
    const int gsmem = 4 * 128 * GK * (int)sizeof(float);
    cudaFuncSetAttribute(tf32_gemm_gates, cudaFuncAttributeMaxDynamicSharedMemorySize, gsmem);
    tf32_gemm_gates<<<dim3(HX4 / 128, (BB * SS) / 128), 256, gsmem>>>(b_ih, b_hh, gates);

    // 2. persistent LSTM (R15)
    const int smem = (32 * WSTRIDE * 2 + 16 * WSTRIDE * 2) * (int)sizeof(__nv_bfloat16)
                   + (8 * 16 * 36 + 128) * (int)sizeof(float);
    cudaFuncSetAttribute(lstm_kernel, cudaFuncAttributeMaxDynamicSharedMemorySize, smem);
    lstm_kernel<<<NCTA, 256, smem>>>(W_hh);

    // 3. span pool + LN
    pool_ln_kernel<<<BB * NSPAN, 256>>>(ln_g, ln_b, heads, tails);

    // 4. fused QKV projections (tf32)
    mma_gemm_qkv<<<dim3(HH / 128, (BB * NSPAN) / 128, 3), 256>>>(
        pool, Wq, Wk, Wv, bq, bk, bv, q, k, v);

    // 5. attention
    attn_kernel<<<BB * NHEADS, 128>>>(mask);

    // 6. output projection (tf32)
    mma_gemm_nt<<<dim3(HH / 128, (BB * NSPAN) / 128), 256>>>(ctx, Wo, bo, nullptr, wo_buf, HH, HH);

    // 7. residual LN
    ln_res_kernel<<<BB * NSPAN, 256>>>(aln_g, aln_b);

    // 8. classifier -> d_out [B,NS,L]
    clf_kernel<<<(BB * NSPAN) / 8, 256>>>(clf_W, clf_b, out);
}